// round 5
// baseline (speedup 1.0000x reference)
#include <cuda_runtime.h>
#include <cuda_bf16.h>
#include <math.h>

#define B_  32
#define S_  1024
#define E_  64
#define H_  4
#define HD_ 16
#define HID_ 256
#define AD_ 32
#define NS_ 64
#define NT_ (B_*S_)   // 32768 tokens

// ---------------- scratch (no allocations allowed) ----------------
__device__ float g_q[B_*H_*S_*HD_];
__device__ float g_k[B_*H_*S_*HD_];
__device__ float g_v[B_*H_*S_*HD_];
__device__ float g_o[B_*S_*E_];
__device__ unsigned long long g_hid[(NT_/2)*HID_];   // token-pair packed GELU output (32MB)

// ---------------- packed f32x2 helpers ----------------
__device__ __forceinline__ unsigned long long pk2(float lo, float hi) {
    unsigned long long r;
    asm("mov.b64 %0,{%1,%2};" : "=l"(r) : "f"(lo), "f"(hi));
    return r;
}
__device__ __forceinline__ float2 upk2(unsigned long long v) {
    float2 f;
    asm("mov.b64 {%0,%1},%2;" : "=f"(f.x), "=f"(f.y) : "l"(v));
    return f;
}
__device__ __forceinline__ unsigned long long ffma2_(unsigned long long a,
                                                     unsigned long long b,
                                                     unsigned long long c) {
    unsigned long long d;
    asm("fma.rn.f32x2 %0,%1,%2,%3;" : "=l"(d) : "l"(a), "l"(b), "l"(c));
    return d;
}
__device__ __forceinline__ unsigned long long fmul2_(unsigned long long a,
                                                     unsigned long long b) {
    unsigned long long d;
    asm("mul.rn.f32x2 %0,%1,%2;" : "=l"(d) : "l"(a), "l"(b));
    return d;
}
__device__ __forceinline__ float gelu_(float v) {
    return 0.5f * v * (1.f + erff(v * 0.70710678118654752f));
}

// ======================= kernel 1: rmsnorm + QKV =======================
__global__ void __launch_bounds__(256) qkv_kernel(
    const float* __restrict__ x, const float* __restrict__ nw,
    const float* __restrict__ wq, const float* __restrict__ wk,
    const float* __restrict__ wv)
{
    extern __shared__ float sm[];
    float* ws  = sm;                 // 3 * 64*66
    float* nws = ws + 3*4224;        // 64
    unsigned long long* htp_all = (unsigned long long*)(nws + 64); // 8 warps * 128 u64

    const int tid = threadIdx.x, lane = tid & 31, w = tid >> 5;

    for (int i = tid; i < 64*64; i += blockDim.x) {
        int e = i >> 6, j = i & 63;
        ws[0*4224 + e*66 + j] = wq[i];
        ws[1*4224 + e*66 + j] = wk[i];
        ws[2*4224 + e*66 + j] = wv[i];
    }
    if (tid < 64) nws[tid] = nw[tid];
    __syncthreads();

    unsigned long long* htp = htp_all + w*128;   // [tp*64 + j]
    float* hview = (float*)htp;

    for (int chunk = blockIdx.x*8 + w; chunk < NT_/4; chunk += gridDim.x*8) {
        const int tok0 = chunk*4;
        #pragma unroll
        for (int t = 0; t < 4; t++) {
            float xa = x[(tok0+t)*64 + lane];
            float xb = x[(tok0+t)*64 + lane + 32];
            float ss = xa*xa + xb*xb;
            #pragma unroll
            for (int o = 16; o; o >>= 1) ss += __shfl_xor_sync(~0u, ss, o);
            float rinv = rsqrtf(ss * (1.f/64.f) + 1e-5f);
            int tp = t >> 1, c = t & 1;
            hview[(tp*64 + lane)*2 + c]      = xa * rinv * nws[lane];
            hview[(tp*64 + lane + 32)*2 + c] = xb * rinv * nws[lane + 32];
        }
        __syncwarp();

        unsigned long long acc[3][2][2];
        #pragma unroll
        for (int p = 0; p < 3; p++)
            #pragma unroll
            for (int r = 0; r < 2; r++) { acc[p][r][0] = 0ull; acc[p][r][1] = 0ull; }

        #pragma unroll 4
        for (int j = 0; j < 64; j += 2) {
            ulonglong2 h0 = *(const ulonglong2*)(htp + j);
            ulonglong2 h1 = *(const ulonglong2*)(htp + 64 + j);
            #pragma unroll
            for (int p = 0; p < 3; p++)
                #pragma unroll
                for (int r = 0; r < 2; r++) {
                    float2 wf = *(const float2*)(ws + p*4224 + (lane + r*32)*66 + j);
                    unsigned long long wx = pk2(wf.x, wf.x);
                    unsigned long long wy = pk2(wf.y, wf.y);
                    acc[p][r][0] = ffma2_(wx, h0.x, acc[p][r][0]);
                    acc[p][r][0] = ffma2_(wy, h0.y, acc[p][r][0]);
                    acc[p][r][1] = ffma2_(wx, h1.x, acc[p][r][1]);
                    acc[p][r][1] = ffma2_(wy, h1.y, acc[p][r][1]);
                }
        }

        const int b0 = tok0 >> 10, s0 = tok0 & 1023;
        #pragma unroll
        for (int p = 0; p < 3; p++) {
            float* dst = (p == 0) ? g_q : (p == 1 ? g_k : g_v);
            #pragma unroll
            for (int r = 0; r < 2; r++) {
                int e = lane + r*32, hh = e >> 4, d = e & 15;
                float* base = dst + ((b0*H_ + hh)*S_)*HD_ + d;
                #pragma unroll
                for (int tp = 0; tp < 2; tp++) {
                    float2 v = upk2(acc[p][r][tp]);
                    base[(s0 + tp*2    )*HD_] = v.x;
                    base[(s0 + tp*2 + 1)*HD_] = v.y;
                }
            }
        }
        __syncwarp();
    }
}

// ======================= kernel 2: causal attention v2 =======================
// one block per (b,h): 512 threads. Thread t owns queries qa=t and qb=1023-t
// (exactly 1025 key visits per thread -> perfect balance). Full K/V preload.
__global__ void __launch_bounds__(512, 1) attn_kernel()
{
    const int bh = blockIdx.x;               // 0..127
    extern __shared__ float sm[];
    float* Ks = sm;                          // 1024*16
    float* Vs = sm + 16384;

    {   // full preload, coalesced
        const float4* kg4 = (const float4*)(g_k + bh * S_ * HD_);
        const float4* vg4 = (const float4*)(g_v + bh * S_ * HD_);
        float4* Ks4 = (float4*)Ks;
        float4* Vs4 = (float4*)Vs;
        for (int i = threadIdx.x; i < 4096; i += 512) { Ks4[i] = kg4[i]; Vs4[i] = vg4[i]; }
    }
    __syncthreads();

    const int t  = threadIdx.x;              // qa
    const int qb = 1023 - t;
    const float qsc = 0.25f * 1.4426950408889634f;

    unsigned long long q2a[8], q2b[8];
    {
        const float* qpa = g_q + (bh*S_ + t) * HD_;
        const float* qpb = g_q + (bh*S_ + qb) * HD_;
        #pragma unroll
        for (int d = 0; d < 8; d++) {
            q2a[d] = pk2(qpa[2*d] * qsc, qpa[2*d+1] * qsc);
            q2b[d] = pk2(qpb[2*d] * qsc, qpb[2*d+1] * qsc);
        }
    }

    float ma = -1e30f, la = 0.f, mb = -1e30f, lb = 0.f;
    unsigned long long acca[8], accb[8];
    #pragma unroll
    for (int d = 0; d < 8; d++) { acca[d] = 0ull; accb[d] = 0ull; }

    const int tbase     = t & ~31;
    const int loop1_end = tbase + 32;        // j in [0, loop1_end): qb always active
    const int loop2_end = 1024 - tbase;      // j in [loop1_end, loop2_end): qb predicated

    // ---- phase 1: both queries ----
    #pragma unroll 2
    for (int j = 0; j < loop1_end; j++) {
        const ulonglong2* kb = (const ulonglong2*)(Ks + j*16);
        ulonglong2 k0 = kb[0], k1 = kb[1], k2 = kb[2], k3 = kb[3];
        unsigned long long pa = fmul2_(q2a[0], k0.x);
        unsigned long long pb = fmul2_(q2b[0], k0.x);
        pa = ffma2_(q2a[1], k0.y, pa);  pb = ffma2_(q2b[1], k0.y, pb);
        pa = ffma2_(q2a[2], k1.x, pa);  pb = ffma2_(q2b[2], k1.x, pb);
        pa = ffma2_(q2a[3], k1.y, pa);  pb = ffma2_(q2b[3], k1.y, pb);
        pa = ffma2_(q2a[4], k2.x, pa);  pb = ffma2_(q2b[4], k2.x, pb);
        pa = ffma2_(q2a[5], k2.y, pa);  pb = ffma2_(q2b[5], k2.y, pb);
        pa = ffma2_(q2a[6], k3.x, pa);  pb = ffma2_(q2b[6], k3.x, pb);
        pa = ffma2_(q2a[7], k3.y, pa);  pb = ffma2_(q2b[7], k3.y, pb);
        float2 fa = upk2(pa); float sa = fa.x + fa.y;
        float2 fb = upk2(pb); float sb = fb.x + fb.y;

        const ulonglong2* vb4 = (const ulonglong2*)(Vs + j*16);
        ulonglong2 v0 = vb4[0], v1 = vb4[1], v2 = vb4[2], v3 = vb4[3];

        // qb (always active in this phase)
        if (sb > mb) {
            float c = exp2f(mb - sb);
            lb *= c;
            unsigned long long c2 = pk2(c, c);
            #pragma unroll
            for (int d = 0; d < 8; d++) accb[d] = fmul2_(accb[d], c2);
            mb = sb;
        }
        float pbv = exp2f(sb - mb);
        lb += pbv;
        unsigned long long pb2 = pk2(pbv, pbv);
        accb[0] = ffma2_(pb2, v0.x, accb[0]);
        accb[1] = ffma2_(pb2, v0.y, accb[1]);
        accb[2] = ffma2_(pb2, v1.x, accb[2]);
        accb[3] = ffma2_(pb2, v1.y, accb[3]);
        accb[4] = ffma2_(pb2, v2.x, accb[4]);
        accb[5] = ffma2_(pb2, v2.y, accb[5]);
        accb[6] = ffma2_(pb2, v3.x, accb[6]);
        accb[7] = ffma2_(pb2, v3.y, accb[7]);

        // qa (predicated on causal bound)
        if (j <= t) {
            if (sa > ma) {
                float c = exp2f(ma - sa);
                la *= c;
                unsigned long long c2 = pk2(c, c);
                #pragma unroll
                for (int d = 0; d < 8; d++) acca[d] = fmul2_(acca[d], c2);
                ma = sa;
            }
            float pav = exp2f(sa - ma);
            la += pav;
            unsigned long long pa2 = pk2(pav, pav);
            acca[0] = ffma2_(pa2, v0.x, acca[0]);
            acca[1] = ffma2_(pa2, v0.y, acca[1]);
            acca[2] = ffma2_(pa2, v1.x, acca[2]);
            acca[3] = ffma2_(pa2, v1.y, acca[3]);
            acca[4] = ffma2_(pa2, v2.x, acca[4]);
            acca[5] = ffma2_(pa2, v2.y, acca[5]);
            acca[6] = ffma2_(pa2, v3.x, acca[6]);
            acca[7] = ffma2_(pa2, v3.y, acca[7]);
        }
    }

    // ---- phase 2: only qb ----
    #pragma unroll 2
    for (int j = loop1_end; j < loop2_end; j++) {
        const ulonglong2* kb = (const ulonglong2*)(Ks + j*16);
        ulonglong2 k0 = kb[0], k1 = kb[1], k2 = kb[2], k3 = kb[3];
        unsigned long long pb = fmul2_(q2b[0], k0.x);
        pb = ffma2_(q2b[1], k0.y, pb);
        pb = ffma2_(q2b[2], k1.x, pb);
        pb = ffma2_(q2b[3], k1.y, pb);
        pb = ffma2_(q2b[4], k2.x, pb);
        pb = ffma2_(q2b[5], k2.y, pb);
        pb = ffma2_(q2b[6], k3.x, pb);
        pb = ffma2_(q2b[7], k3.y, pb);
        float2 fb = upk2(pb); float sb = fb.x + fb.y;

        if (j <= qb) {
            const ulonglong2* vb4 = (const ulonglong2*)(Vs + j*16);
            ulonglong2 v0 = vb4[0], v1 = vb4[1], v2 = vb4[2], v3 = vb4[3];
            if (sb > mb) {
                float c = exp2f(mb - sb);
                lb *= c;
                unsigned long long c2 = pk2(c, c);
                #pragma unroll
                for (int d = 0; d < 8; d++) accb[d] = fmul2_(accb[d], c2);
                mb = sb;
            }
            float pbv = exp2f(sb - mb);
            lb += pbv;
            unsigned long long pb2 = pk2(pbv, pbv);
            accb[0] = ffma2_(pb2, v0.x, accb[0]);
            accb[1] = ffma2_(pb2, v0.y, accb[1]);
            accb[2] = ffma2_(pb2, v1.x, accb[2]);
            accb[3] = ffma2_(pb2, v1.y, accb[3]);
            accb[4] = ffma2_(pb2, v2.x, accb[4]);
            accb[5] = ffma2_(pb2, v2.y, accb[5]);
            accb[6] = ffma2_(pb2, v3.x, accb[6]);
            accb[7] = ffma2_(pb2, v3.y, accb[7]);
        }
    }

    const int b = bh >> 2, h = bh & 3;
    {
        float inv = 1.f / la;
        float* op = g_o + (b*S_ + t)*E_ + h*16;
        #pragma unroll
        for (int d = 0; d < 8; d++) {
            float2 a = upk2(acca[d]);
            op[2*d]   = a.x * inv;
            op[2*d+1] = a.y * inv;
        }
    }
    {
        float inv = 1.f / lb;
        float* op = g_o + (b*S_ + qb)*E_ + h*16;
        #pragma unroll
        for (int d = 0; d < 8; d++) {
            float2 a = upk2(accb[d]);
            op[2*d]   = a.x * inv;
            op[2*d+1] = a.y * inv;
        }
    }
}

// ======================= kernel 3: wo-proj + residual + memory read =======================
__global__ void __launch_bounds__(256) mem_kernel(
    const float* __restrict__ x,     const float* __restrict__ mvals,
    const float* __restrict__ maddr, const float* __restrict__ mnw,
    const float* __restrict__ wo,    const float* __restrict__ mq,
    const float* __restrict__ mo,    float* __restrict__ out)
{
    extern __shared__ float sm[];
    float* woT  = sm;              // 64*65
    float* moT  = woT + 4160;      // 64*65
    float* mqT  = moT + 4160;      // 64*33
    float* aT   = mqT + 2112;      // 32*65
    float* mnws = aT + 2080;       // 64
    float* rows = mnws + 64;       // 8 * 96

    const int tid = threadIdx.x, lane = tid & 31, w = tid >> 5;

    for (int i = tid; i < 4096; i += blockDim.x) {
        int e = i >> 6, j = i & 63;
        woT[j*65 + e] = wo[i];
        moT[j*65 + e] = mo[i];
    }
    for (int i = tid; i < AD_*E_; i += blockDim.x) {
        int a = i >> 6, e = i & 63;
        mqT[e*33 + a] = mq[i];
    }
    if (tid < 64) mnws[tid] = mnw[tid];
    if (tid < 64) {
        float ssum = 0.f, v[32];
        #pragma unroll
        for (int a = 0; a < 32; a++) { v[a] = maddr[tid*32 + a]; ssum += v[a]*v[a]; }
        float rn = 1.f / fmaxf(sqrtf(ssum), 1e-12f);
        #pragma unroll
        for (int a = 0; a < 32; a++) aT[a*65 + tid] = v[a] * rn;
    }
    __syncthreads();

    float* hrow = rows + w*96;
    float* qrow = hrow + 64;

    for (int tok = blockIdx.x*8 + w; tok < NT_; tok += gridDim.x*8) {
        const int b = tok >> 10;
        hrow[lane]      = g_o[tok*64 + lane];
        hrow[lane + 32] = g_o[tok*64 + lane + 32];
        __syncwarp();
        float x1a = x[tok*64 + lane], x1b = x[tok*64 + lane + 32];
        {
            float s0 = 0.f, s1 = 0.f;
            #pragma unroll
            for (int j = 0; j < 64; j++) {
                float hv = hrow[j];
                s0 += hv * woT[j*65 + lane];
                s1 += hv * woT[j*65 + lane + 32];
            }
            x1a += s0; x1b += s1;
        }
        __syncwarp();
        float ss = x1a*x1a + x1b*x1b;
        #pragma unroll
        for (int o = 16; o; o >>= 1) ss += __shfl_xor_sync(~0u, ss, o);
        float rinv = rsqrtf(ss * (1.f/64.f) + 1e-5f);
        hrow[lane]      = x1a * rinv * mnws[lane];
        hrow[lane + 32] = x1b * rinv * mnws[lane + 32];
        __syncwarp();
        float qa = 0.f;
        #pragma unroll
        for (int e = 0; e < 64; e++) qa += hrow[e] * mqT[e*33 + lane];
        float qsm = qa*qa;
        #pragma unroll
        for (int o = 16; o; o >>= 1) qsm += __shfl_xor_sync(~0u, qsm, o);
        float rq = 1.f / fmaxf(sqrtf(qsm), 1e-12f);
        qrow[lane] = qa * rq;
        __syncwarp();
        float sc0 = 0.f, sc1 = 0.f;
        #pragma unroll
        for (int a = 0; a < 32; a++) {
            float qv = qrow[a];
            sc0 += qv * aT[a*65 + lane];
            sc1 += qv * aT[a*65 + lane + 32];
        }
        sc0 *= 4.f; sc1 *= 4.f;
        float tv[8]; int ti[8];
        float c0 = sc0, c1 = sc1; int i0 = lane, i1 = lane + 32;
        #pragma unroll
        for (int k = 0; k < 8; k++) {
            float bv; int bidx;
            if (c0 > c1 || (c0 == c1 && i0 < i1)) { bv = c0; bidx = i0; }
            else                                   { bv = c1; bidx = i1; }
            #pragma unroll
            for (int o = 16; o; o >>= 1) {
                float ov = __shfl_xor_sync(~0u, bv, o);
                int   oi = __shfl_xor_sync(~0u, bidx, o);
                if (ov > bv || (ov == bv && oi < bidx)) { bv = ov; bidx = oi; }
            }
            tv[k] = bv; ti[k] = bidx;
            if (bidx == i0) c0 = -1e30f;
            if (bidx == i1) c1 = -1e30f;
        }
        float wsum = 0.f, wk8[8];
        #pragma unroll
        for (int k = 0; k < 8; k++) { wk8[k] = __expf(tv[k] - tv[0]); wsum += wk8[k]; }
        float winv = 1.f / wsum;
        const float* mb = mvals + b * NS_ * E_;
        float r0 = 0.f, r1 = 0.f;
        #pragma unroll
        for (int k = 0; k < 8; k++) {
            float wv = wk8[k] * winv;
            const float* mrow = mb + ti[k]*64;
            r0 += wv * mrow[lane];
            r1 += wv * mrow[lane + 32];
        }
        hrow[lane] = r0; hrow[lane + 32] = r1;
        __syncwarp();
        float o0 = 0.f, o1 = 0.f;
        #pragma unroll
        for (int j = 0; j < 64; j++) {
            float rv = hrow[j];
            o0 += rv * moT[j*65 + lane];
            o1 += rv * moT[j*65 + lane + 32];
        }
        out[tok*64 + lane]      = x1a + o0;
        out[tok*64 + lane + 32] = x1b + o1;
        __syncwarp();
    }
}

// ======================= kernel 4a: FFN GEMM1 + GELU -> g_hid =======================
// warp = 8 tokens (4 packed token-pairs). Small smem -> 2 blocks/SM.
__global__ void __launch_bounds__(256) ffn1_kernel(
    const float* __restrict__ fnw, const float* __restrict__ w1,
    const float* __restrict__ b1,  const float* __restrict__ out)
{
    extern __shared__ float sm[];
    float* w1s = sm;                 // 256*66 = 16896
    float* b1s = w1s + 16896;        // 256
    float* fns = b1s + 256;          // 64
    unsigned long long* u64base = (unsigned long long*)(fns + 64);  // 8 warps * 256 u64

    const int tid = threadIdx.x, lane = tid & 31, w = tid >> 5;

    for (int i = tid; i < HID_*E_; i += blockDim.x) {
        int o = i >> 6, j = i & 63;
        w1s[o*66 + j] = w1[i];
    }
    if (tid < 256) b1s[tid] = b1[tid];
    if (tid < 64) fns[tid] = fnw[tid];
    __syncthreads();

    unsigned long long* htp = u64base + w*256;
    float* hview = (float*)htp;

    for (int chunk = blockIdx.x*8 + w; chunk < NT_/8; chunk += gridDim.x*8) {
        const int tok0 = chunk*8;
        #pragma unroll
        for (int t = 0; t < 8; t++) {
            float xa = out[(tok0+t)*64 + lane];
            float xb = out[(tok0+t)*64 + lane + 32];
            float ss = xa*xa + xb*xb;
            #pragma unroll
            for (int o = 16; o; o >>= 1) ss += __shfl_xor_sync(~0u, ss, o);
            float rinv = rsqrtf(ss * (1.f/64.f) + 1e-5f);
            int tp = t >> 1, c = t & 1;
            hview[(tp*64 + lane)*2 + c]      = xa * rinv * fns[lane];
            hview[(tp*64 + lane + 32)*2 + c] = xb * rinv * fns[lane + 32];
        }
        __syncwarp();

        unsigned long long acc[4][8];
        #pragma unroll
        for (int tp = 0; tp < 4; tp++)
            #pragma unroll
            for (int r = 0; r < 8; r++) acc[tp][r] = 0ull;

        #pragma unroll 4
        for (int j = 0; j < 64; j += 2) {
            ulonglong2 hh[4];
            #pragma unroll
            for (int tp = 0; tp < 4; tp++)
                hh[tp] = *(const ulonglong2*)(htp + tp*64 + j);
            #pragma unroll
            for (int r = 0; r < 8; r++) {
                float2 wf = *(const float2*)(w1s + (lane + r*32)*66 + j);
                unsigned long long wx = pk2(wf.x, wf.x);
                unsigned long long wy = pk2(wf.y, wf.y);
                #pragma unroll
                for (int tp = 0; tp < 4; tp++) {
                    acc[tp][r] = ffma2_(wx, hh[tp].x, acc[tp][r]);
                    acc[tp][r] = ffma2_(wy, hh[tp].y, acc[tp][r]);
                }
            }
        }

        // bias + exact GELU -> g_hid (token-pair packed, coalesced)
        unsigned long long* gh = g_hid + (tok0 >> 1) * HID_;
        #pragma unroll
        for (int r = 0; r < 8; r++) {
            int o = lane + r*32;
            float bb = b1s[o];
            #pragma unroll
            for (int tp = 0; tp < 4; tp++) {
                float2 v = upk2(acc[tp][r]);
                gh[tp*256 + o] = pk2(gelu_(v.x + bb), gelu_(v.y + bb));
            }
        }
        __syncwarp();
    }
}

// ======================= kernel 4b: FFN GEMM2 + residual =======================
__global__ void __launch_bounds__(256) ffn2_kernel(
    const float* __restrict__ w2, const float* __restrict__ b2,
    float* __restrict__ out)
{
    extern __shared__ float sm[];
    float* w2s = sm;                 // 64*258 = 16512
    float* b2s = w2s + 16512;        // 64

    const int tid = threadIdx.x, lane = tid & 31, w = tid >> 5;

    for (int i = tid; i < E_*HID_; i += blockDim.x) {
        int e = i >> 8, o = i & 255;
        w2s[e*258 + o] = w2[i];
    }
    if (tid < 64) b2s[tid] = b2[tid];
    __syncthreads();

    const float* w2a = w2s + lane*258;
    const float* w2b = w2s + (lane + 32)*258;

    for (int chunk = blockIdx.x*8 + w; chunk < NT_/8; chunk += gridDim.x*8) {
        const int tok0 = chunk*8;
        const unsigned long long* gh = g_hid + (tok0 >> 1) * HID_;

        unsigned long long a2[4][2];
        #pragma unroll
        for (int tp = 0; tp < 4; tp++) { a2[tp][0] = 0ull; a2[tp][1] = 0ull; }

        #pragma unroll 4
        for (int o = 0; o < 256; o += 2) {
            float2 wa = *(const float2*)(w2a + o);
            float2 wb = *(const float2*)(w2b + o);
            unsigned long long wax = pk2(wa.x, wa.x), way = pk2(wa.y, wa.y);
            unsigned long long wbx = pk2(wb.x, wb.x), wby = pk2(wb.y, wb.y);
            #pragma unroll
            for (int tp = 0; tp < 4; tp++) {
                ulonglong2 hh = *(const ulonglong2*)(gh + tp*256 + o);
                a2[tp][0] = ffma2_(wax, hh.x, a2[tp][0]);
                a2[tp][0] = ffma2_(way, hh.y, a2[tp][0]);
                a2[tp][1] = ffma2_(wbx, hh.x, a2[tp][1]);
                a2[tp][1] = ffma2_(wby, hh.y, a2[tp][1]);
            }
        }

        #pragma unroll
        for (int tp = 0; tp < 4; tp++) {
            float2 v0 = upk2(a2[tp][0]);
            float2 v1 = upk2(a2[tp][1]);
            int t0 = tok0 + 2*tp;
            out[t0*64 + lane]          += b2s[lane]      + v0.x;
            out[(t0+1)*64 + lane]      += b2s[lane]      + v0.y;
            out[t0*64 + lane + 32]     += b2s[lane + 32] + v1.x;
            out[(t0+1)*64 + lane + 32] += b2s[lane + 32] + v1.y;
        }
    }
}

// ======================= launch =======================
extern "C" void kernel_launch(void* const* d_in, const int* in_sizes, int n_in,
                              void* d_out, int out_size)
{
    const float* x     = (const float*)d_in[0];
    const float* maddr = (const float*)d_in[1];
    const float* mvals = (const float*)d_in[2];
    const float* anw   = (const float*)d_in[3];
    const float* wq    = (const float*)d_in[4];
    const float* wk    = (const float*)d_in[5];
    const float* wv    = (const float*)d_in[6];
    const float* wo    = (const float*)d_in[7];
    const float* mnw   = (const float*)d_in[8];
    const float* mq    = (const float*)d_in[9];
    const float* mo    = (const float*)d_in[10];
    const float* fnw   = (const float*)d_in[11];
    const float* w1    = (const float*)d_in[12];
    const float* b1    = (const float*)d_in[13];
    const float* w2    = (const float*)d_in[14];
    const float* b2    = (const float*)d_in[15];
    float* out = (float*)d_out;

    const int QKV_SMEM  = (3*4224 + 64) * 4 + 8*128*8;   // 59,136 B
    const int ATT_SMEM  = 32768 * 4;                     // 131,072 B
    const int MEM_SMEM  = (4160*2 + 2112 + 2080 + 64 + 8*96) * 4;  // 53,376 B
    const int FFN1_SMEM = (16896 + 256 + 64) * 4 + 8*256*8;        // 85,248 B
    const int FFN2_SMEM = (16512 + 64) * 4;                        // 66,304 B

    cudaFuncSetAttribute(qkv_kernel, cudaFuncAttributeMaxDynamicSharedMemorySize, QKV_SMEM);
    cudaFuncSetAttribute(attn_kernel, cudaFuncAttributeMaxDynamicSharedMemorySize, ATT_SMEM);
    cudaFuncSetAttribute(mem_kernel, cudaFuncAttributeMaxDynamicSharedMemorySize, MEM_SMEM);
    cudaFuncSetAttribute(ffn1_kernel, cudaFuncAttributeMaxDynamicSharedMemorySize, FFN1_SMEM);
    cudaFuncSetAttribute(ffn2_kernel, cudaFuncAttributeMaxDynamicSharedMemorySize, FFN2_SMEM);

    qkv_kernel<<<296, 256, QKV_SMEM>>>(x, anw, wq, wk, wv);
    attn_kernel<<<128, 512, ATT_SMEM>>>();
    mem_kernel<<<592, 256, MEM_SMEM>>>(x, mvals, maddr, mnw, wo, mq, mo, out);
    ffn1_kernel<<<296, 256, FFN1_SMEM>>>(fnw, w1, b1, out);
    ffn2_kernel<<<296, 256, FFN2_SMEM>>>(w2, b2, out);
}

// round 7
// speedup vs baseline: 1.6400x; 1.6400x over previous
#include <cuda_runtime.h>
#include <cuda_bf16.h>
#include <math.h>

#define B_  32
#define S_  1024
#define E_  64
#define H_  4
#define HD_ 16
#define HID_ 256
#define AD_ 32
#define NS_ 64
#define NT_ (B_*S_)
#define QSCALE (0.25f * 1.4426950408889634f)

__device__ __align__(16) __nv_bfloat16 g_qh[B_*H_*S_*HD_];  // [bh][s][d], pre-scaled
__device__ __align__(16) __nv_bfloat16 g_kh[B_*H_*S_*HD_];  // [bh][s][d]
__device__ __align__(16) __nv_bfloat16 g_vt[B_*H_*HD_*S_];  // [bh][d][s]
__device__ float g_o[B_*S_*E_];
__device__ unsigned long long g_hid[(NT_/2)*HID_];

__device__ __forceinline__ unsigned long long pk2(float lo, float hi) {
    unsigned long long r; asm("mov.b64 %0,{%1,%2};" : "=l"(r) : "f"(lo), "f"(hi)); return r;
}
__device__ __forceinline__ float2 upk2(unsigned long long v) {
    float2 f; asm("mov.b64 {%0,%1},%2;" : "=f"(f.x), "=f"(f.y) : "l"(v)); return f;
}
__device__ __forceinline__ unsigned long long ffma2_(unsigned long long a,
    unsigned long long b, unsigned long long c) {
    unsigned long long d;
    asm("fma.rn.f32x2 %0,%1,%2,%3;" : "=l"(d) : "l"(a), "l"(b), "l"(c)); return d;
}
__device__ __forceinline__ float gelu_(float v) {
    return 0.5f * v * (1.f + erff(v * 0.70710678118654752f));
}
__device__ __forceinline__ float ex2_(float x) {
    float y; asm("ex2.approx.f32 %0,%1;" : "=f"(y) : "f"(x)); return y;
}
__device__ __forceinline__ unsigned pbf_(float lo, float hi) {
    unsigned r; asm("cvt.rn.bf16x2.f32 %0,%1,%2;" : "=r"(r) : "f"(hi), "f"(lo)); return r;
}
__device__ __forceinline__ void mma16816(float& c0, float& c1, float& c2, float& c3,
    unsigned a0, unsigned a1, unsigned a2, unsigned a3, unsigned b0, unsigned b1) {
    asm volatile("mma.sync.aligned.m16n8k16.row.col.f32.bf16.bf16.f32 "
        "{%0,%1,%2,%3},{%4,%5,%6,%7},{%8,%9},{%0,%1,%2,%3};"
        : "+f"(c0), "+f"(c1), "+f"(c2), "+f"(c3)
        : "r"(a0), "r"(a1), "r"(a2), "r"(a3), "r"(b0), "r"(b1));
}

// ============ kernel 1: rmsnorm + QKV (bf16 out, V transposed) ============
__global__ void __launch_bounds__(256) qkv_kernel(
    const float* __restrict__ x, const float* __restrict__ nw,
    const float* __restrict__ wq, const float* __restrict__ wk,
    const float* __restrict__ wv)
{
    extern __shared__ float sm[];
    float* ws  = sm;                 // 3*64*66
    float* nws = ws + 3*4224;
    unsigned long long* htp_all = (unsigned long long*)(nws + 64);

    const int tid = threadIdx.x, lane = tid & 31, w = tid >> 5;

    for (int i = tid; i < 64*64; i += blockDim.x) {
        int e = i >> 6, j = i & 63;
        ws[0*4224 + e*66 + j] = wq[i];
        ws[1*4224 + e*66 + j] = wk[i];
        ws[2*4224 + e*66 + j] = wv[i];
    }
    if (tid < 64) nws[tid] = nw[tid];
    __syncthreads();

    unsigned long long* htp = htp_all + w*128;
    float* hview = (float*)htp;

    for (int chunk = blockIdx.x*8 + w; chunk < NT_/4; chunk += gridDim.x*8) {
        const int tok0 = chunk*4;
        #pragma unroll
        for (int t = 0; t < 4; t++) {
            float xa = x[(tok0+t)*64 + lane];
            float xb = x[(tok0+t)*64 + lane + 32];
            float ss = xa*xa + xb*xb;
            #pragma unroll
            for (int o = 16; o; o >>= 1) ss += __shfl_xor_sync(~0u, ss, o);
            float rinv = rsqrtf(ss * (1.f/64.f) + 1e-5f);
            int tp = t >> 1, c = t & 1;
            hview[(tp*64 + lane)*2 + c]      = xa * rinv * nws[lane];
            hview[(tp*64 + lane + 32)*2 + c] = xb * rinv * nws[lane + 32];
        }
        __syncwarp();

        unsigned long long acc[3][2][2];
        #pragma unroll
        for (int p = 0; p < 3; p++)
            #pragma unroll
            for (int r = 0; r < 2; r++) { acc[p][r][0] = 0ull; acc[p][r][1] = 0ull; }

        #pragma unroll 4
        for (int j = 0; j < 64; j += 2) {
            ulonglong2 h0 = *(const ulonglong2*)(htp + j);
            ulonglong2 h1 = *(const ulonglong2*)(htp + 64 + j);
            #pragma unroll
            for (int p = 0; p < 3; p++)
                #pragma unroll
                for (int r = 0; r < 2; r++) {
                    float2 wf = *(const float2*)(ws + p*4224 + (lane + r*32)*66 + j);
                    unsigned long long wx = pk2(wf.x, wf.x);
                    unsigned long long wy = pk2(wf.y, wf.y);
                    acc[p][r][0] = ffma2_(wx, h0.x, acc[p][r][0]);
                    acc[p][r][0] = ffma2_(wy, h0.y, acc[p][r][0]);
                    acc[p][r][1] = ffma2_(wx, h1.x, acc[p][r][1]);
                    acc[p][r][1] = ffma2_(wy, h1.y, acc[p][r][1]);
                }
        }

        const int b0 = tok0 >> 10, s0 = tok0 & 1023;
        #pragma unroll
        for (int r = 0; r < 2; r++) {
            int e = lane + r*32, hh = e >> 4, d = e & 15;
            size_t bhi = (size_t)(b0*H_ + hh);
            #pragma unroll
            for (int tp = 0; tp < 2; tp++) {
                int s = s0 + tp*2;
                float2 vq = upk2(acc[0][r][tp]);
                g_qh[(bhi*S_ + s  )*16 + d] = __float2bfloat16(vq.x * QSCALE);
                g_qh[(bhi*S_ + s+1)*16 + d] = __float2bfloat16(vq.y * QSCALE);
                float2 vk = upk2(acc[1][r][tp]);
                g_kh[(bhi*S_ + s  )*16 + d] = __float2bfloat16(vk.x);
                g_kh[(bhi*S_ + s+1)*16 + d] = __float2bfloat16(vk.y);
                float2 vv = upk2(acc[2][r][tp]);
                *(unsigned*)&g_vt[(bhi*16 + d)*S_ + s] = pbf_(vv.x, vv.y);
            }
        }
        __syncwarp();
    }
}

// ============ kernel 2: causal attention via bf16 HMMA ============
// block = (bh, 128-query tile); 4 warps x 32 rows. Whole K + V^T in smem.
// Scores bounded -> no online max: p = exp2(s), divide by row-sum at end.
__global__ void __launch_bounds__(128, 3) attn_kernel()
{
    const int bidx = blockIdx.x;
    const int qt = 7 - (bidx >> 7);          // heavy tiles first
    const int bh = bidx & 127;
    const int nk = (qt + 1) * 128;
    const int qbase = qt * 128;

    extern __shared__ char smc[];
    __nv_bfloat16* Ks = (__nv_bfloat16*)smc;                    // [nk][16]
    __nv_bfloat16* Vt = (__nv_bfloat16*)(smc + 32768);          // [16][1032]
    __nv_bfloat16* Qs = (__nv_bfloat16*)(smc + 32768 + 33024);  // [128][16]

    const int tid = threadIdx.x, lane = tid & 31, w = tid >> 5;

    {
        const uint4* src = (const uint4*)(g_kh + (size_t)bh * S_ * 16);
        uint4* dst = (uint4*)Ks;
        for (int i = tid; i < nk*2; i += 128) dst[i] = src[i];
    }
    {
        const uint4* src = (const uint4*)(g_qh + ((size_t)bh * S_ + qbase) * 16);
        uint4* dst = (uint4*)Qs;
        dst[tid] = src[tid];
        dst[tid + 128] = src[tid + 128];
    }
    for (int d = w; d < 16; d += 4) {
        const uint4* src = (const uint4*)(g_vt + ((size_t)bh*16 + d) * S_);
        uint4* dst = (uint4*)(Vt + d * 1032);
        for (int i = lane; i < nk/8; i += 32) dst[i] = src[i];
    }
    __syncthreads();

    const int g = lane >> 2, tg = lane & 3;

    unsigned qa[2][4];
    #pragma unroll
    for (int mf = 0; mf < 2; mf++) {
        int rr = w*32 + mf*16 + g;
        qa[mf][0] = *(const unsigned*)&Qs[ rr     *16 + 2*tg    ];
        qa[mf][1] = *(const unsigned*)&Qs[(rr + 8)*16 + 2*tg    ];
        qa[mf][2] = *(const unsigned*)&Qs[ rr     *16 + 2*tg + 8];
        qa[mf][3] = *(const unsigned*)&Qs[(rr + 8)*16 + 2*tg + 8];
    }

    float o[2][2][4];
    #pragma unroll
    for (int mf = 0; mf < 2; mf++)
        #pragma unroll
        for (int dh = 0; dh < 2; dh++)
            o[mf][dh][0] = o[mf][dh][1] = o[mf][dh][2] = o[mf][dh][3] = 0.f;
    float lsum[2][2] = {{0.f,0.f},{0.f,0.f}};

    auto step = [&](int j0, bool MASK) {
        unsigned kb[2][2], vb[2][2];
        #pragma unroll
        for (int kh = 0; kh < 2; kh++) {
            const __nv_bfloat16* kr = Ks + (j0 + kh*8 + g)*16 + 2*tg;
            kb[kh][0] = *(const unsigned*)kr;
            kb[kh][1] = *(const unsigned*)(kr + 8);
        }
        #pragma unroll
        for (int dh = 0; dh < 2; dh++) {
            const __nv_bfloat16* vr = Vt + (dh*8 + g)*1032 + j0 + 2*tg;
            vb[dh][0] = *(const unsigned*)vr;
            vb[dh][1] = *(const unsigned*)(vr + 8);
        }
        #pragma unroll
        for (int mf = 0; mf < 2; mf++) {
            float c[2][4];
            #pragma unroll
            for (int kh = 0; kh < 2; kh++) {
                c[kh][0] = c[kh][1] = c[kh][2] = c[kh][3] = 0.f;
                mma16816(c[kh][0], c[kh][1], c[kh][2], c[kh][3],
                         qa[mf][0], qa[mf][1], qa[mf][2], qa[mf][3],
                         kb[kh][0], kb[kh][1]);
            }
            const int r0 = qbase + w*32 + mf*16 + g, r1 = r0 + 8;
            float p[2][4];
            #pragma unroll
            for (int kh = 0; kh < 2; kh++) {
                int k0 = j0 + kh*8 + 2*tg;
                p[kh][0] = (!MASK || k0     <= r0) ? ex2_(c[kh][0]) : 0.f;
                p[kh][1] = (!MASK || k0 + 1 <= r0) ? ex2_(c[kh][1]) : 0.f;
                p[kh][2] = (!MASK || k0     <= r1) ? ex2_(c[kh][2]) : 0.f;
                p[kh][3] = (!MASK || k0 + 1 <= r1) ? ex2_(c[kh][3]) : 0.f;
            }
            lsum[mf][0] += (p[0][0] + p[0][1]) + (p[1][0] + p[1][1]);
            lsum[mf][1] += (p[0][2] + p[0][3]) + (p[1][2] + p[1][3]);
            unsigned pa0 = pbf_(p[0][0], p[0][1]);
            unsigned pa1 = pbf_(p[0][2], p[0][3]);
            unsigned pa2 = pbf_(p[1][0], p[1][1]);
            unsigned pa3 = pbf_(p[1][2], p[1][3]);
            #pragma unroll
            for (int dh = 0; dh < 2; dh++)
                mma16816(o[mf][dh][0], o[mf][dh][1], o[mf][dh][2], o[mf][dh][3],
                         pa0, pa1, pa2, pa3, vb[dh][0], vb[dh][1]);
        }
    };

    for (int j0 = 0; j0 < qbase; j0 += 16) step(j0, false);
    const int wlast = qbase + w*32 + 31;     // last unmasked key for this warp
    for (int j0 = qbase; j0 < nk; j0 += 16) {
        if (j0 > wlast) break;
        step(j0, true);
    }

    const int b = bh >> 2, h = bh & 3;
    #pragma unroll
    for (int mf = 0; mf < 2; mf++) {
        float l0 = lsum[mf][0], l1 = lsum[mf][1];
        l0 += __shfl_xor_sync(~0u, l0, 1); l0 += __shfl_xor_sync(~0u, l0, 2);
        l1 += __shfl_xor_sync(~0u, l1, 1); l1 += __shfl_xor_sync(~0u, l1, 2);
        float i0 = 1.f / l0, i1 = 1.f / l1;
        int r0 = qbase + w*32 + mf*16 + g;
        float* b0p = g_o + ((size_t)(b*S_ + r0))*64 + h*16;
        float* b1p = b0p + 8*64;
        *(float2*)(b0p + 2*tg)     = make_float2(o[mf][0][0]*i0, o[mf][0][1]*i0);
        *(float2*)(b0p + 8 + 2*tg) = make_float2(o[mf][1][0]*i0, o[mf][1][1]*i0);
        *(float2*)(b1p + 2*tg)     = make_float2(o[mf][0][2]*i1, o[mf][0][3]*i1);
        *(float2*)(b1p + 8 + 2*tg) = make_float2(o[mf][1][2]*i1, o[mf][1][3]*i1);
    }
}

// ============ kernel 3: wo-proj + residual + memory read ============
__global__ void __launch_bounds__(256) mem_kernel(
    const float* __restrict__ x,     const float* __restrict__ mvals,
    const float* __restrict__ maddr, const float* __restrict__ mnw,
    const float* __restrict__ wo,    const float* __restrict__ mq,
    const float* __restrict__ mo,    float* __restrict__ out)
{
    extern __shared__ float sm[];
    float* woT  = sm;              // 64*65
    float* moT  = woT + 4160;
    float* mqT  = moT + 4160;      // 64*33
    float* aT   = mqT + 2112;      // 32*65
    float* mnws = aT + 2080;
    float* rows = mnws + 64;       // 8*96

    const int tid = threadIdx.x, lane = tid & 31, w = tid >> 5;

    for (int i = tid; i < 4096; i += blockDim.x) {
        int e = i >> 6, j = i & 63;
        woT[j*65 + e] = wo[i];
        moT[j*65 + e] = mo[i];
    }
    for (int i = tid; i < AD_*E_; i += blockDim.x) {
        int a = i >> 6, e = i & 63;
        mqT[e*33 + a] = mq[i];
    }
    if (tid < 64) mnws[tid] = mnw[tid];
    if (tid < 64) {
        float ssum = 0.f, v[32];
        #pragma unroll
        for (int a = 0; a < 32; a++) { v[a] = maddr[tid*32 + a]; ssum += v[a]*v[a]; }
        float rn = 1.f / fmaxf(sqrtf(ssum), 1e-12f);
        #pragma unroll
        for (int a = 0; a < 32; a++) aT[a*65 + tid] = v[a] * rn;
    }
    __syncthreads();

    float* hrow = rows + w*96;
    float* qrow = hrow + 64;

    for (int tok = blockIdx.x*8 + w; tok < NT_; tok += gridDim.x*8) {
        const int b = tok >> 10;
        hrow[lane]      = g_o[tok*64 + lane];
        hrow[lane + 32] = g_o[tok*64 + lane + 32];
        __syncwarp();
        float x1a = x[tok*64 + lane], x1b = x[tok*64 + lane + 32];
        {
            float s0 = 0.f, s1 = 0.f;
            #pragma unroll
            for (int j = 0; j < 64; j++) {
                float hv = hrow[j];
                s0 += hv * woT[j*65 + lane];
                s1 += hv * woT[j*65 + lane + 32];
            }
            x1a += s0; x1b += s1;
        }
        __syncwarp();
        float ss = x1a*x1a + x1b*x1b;
        #pragma unroll
        for (int o = 16; o; o >>= 1) ss += __shfl_xor_sync(~0u, ss, o);
        float rinv = rsqrtf(ss * (1.f/64.f) + 1e-5f);
        hrow[lane]      = x1a * rinv * mnws[lane];
        hrow[lane + 32] = x1b * rinv * mnws[lane + 32];
        __syncwarp();
        float qa = 0.f;
        #pragma unroll
        for (int e = 0; e < 64; e++) qa += hrow[e] * mqT[e*33 + lane];
        float qsm = qa*qa;
        #pragma unroll
        for (int o = 16; o; o >>= 1) qsm += __shfl_xor_sync(~0u, qsm, o);
        float rq = 1.f / fmaxf(sqrtf(qsm), 1e-12f);
        qrow[lane] = qa * rq;
        __syncwarp();
        float sc0 = 0.f, sc1 = 0.f;
        #pragma unroll
        for (int a = 0; a < 32; a++) {
            float qv = qrow[a];
            sc0 += qv * aT[a*65 + lane];
            sc1 += qv * aT[a*65 + lane + 32];
        }
        sc0 *= 4.f; sc1 *= 4.f;
        // top-8 via warp redux on monotonic keys (low 6 bits = 63-idx tiebreak)
        unsigned f0 = __float_as_uint(sc0);
        unsigned m0 = (f0 & 0x80000000u) ? ~f0 : (f0 | 0x80000000u);
        unsigned key0 = (m0 & 0xFFFFFFC0u) | (unsigned)(63 - lane);
        unsigned f1 = __float_as_uint(sc1);
        unsigned m1 = (f1 & 0x80000000u) ? ~f1 : (f1 | 0x80000000u);
        unsigned key1 = (m1 & 0xFFFFFFC0u) | (unsigned)(31 - lane);
        float tv[8]; int ti[8];
        #pragma unroll
        for (int k = 0; k < 8; k++) {
            unsigned loc = key0 > key1 ? key0 : key1;
            unsigned r = __reduce_max_sync(0xffffffffu, loc);
            int idx = 63 - (int)(r & 63u);
            float vsel = __shfl_sync(0xffffffffu, (idx >= 32) ? sc1 : sc0, idx & 31);
            tv[k] = vsel; ti[k] = idx;
            if (idx == lane)      key0 = 0u;
            if (idx == lane + 32) key1 = 0u;
        }
        float wsum = 0.f, wk8[8];
        #pragma unroll
        for (int k = 0; k < 8; k++) { wk8[k] = __expf(tv[k] - tv[0]); wsum += wk8[k]; }
        float winv = 1.f / wsum;
        const float* mb = mvals + b * NS_ * E_;
        float r0 = 0.f, r1 = 0.f;
        #pragma unroll
        for (int k = 0; k < 8; k++) {
            float wv = wk8[k] * winv;
            const float* mrow = mb + ti[k]*64;
            r0 += wv * mrow[lane];
            r1 += wv * mrow[lane + 32];
        }
        hrow[lane] = r0; hrow[lane + 32] = r1;
        __syncwarp();
        float o0 = 0.f, o1 = 0.f;
        #pragma unroll
        for (int j = 0; j < 64; j++) {
            float rv = hrow[j];
            o0 += rv * moT[j*65 + lane];
            o1 += rv * moT[j*65 + lane + 32];
        }
        out[tok*64 + lane]      = x1a + o0;
        out[tok*64 + lane + 32] = x1b + o1;
        __syncwarp();
    }
}

// ============ kernel 4a: FFN GEMM1 + GELU -> g_hid ============
__global__ void __launch_bounds__(256, 3) ffn1_kernel(
    const float* __restrict__ fnw, const float* __restrict__ w1,
    const float* __restrict__ b1,  const float* __restrict__ out)
{
    extern __shared__ float sm[];
    float* w1s = sm;                 // 256*66
    float* b1s = w1s + 16896;
    float* fns = b1s + 256;
    unsigned long long* u64base = (unsigned long long*)(fns + 64);  // 8w * 128 u64

    const int tid = threadIdx.x, lane = tid & 31, w = tid >> 5;

    for (int i = tid; i < HID_*E_; i += blockDim.x) {
        int o = i >> 6, j = i & 63;
        w1s[o*66 + j] = w1[i];
    }
    if (tid < 256) b1s[tid] = b1[tid];
    if (tid < 64) fns[tid] = fnw[tid];
    __syncthreads();

    unsigned long long* htp = u64base + w*128;
    float* hview = (float*)htp;

    for (int chunk = blockIdx.x*8 + w; chunk < NT_/4; chunk += gridDim.x*8) {
        const int tok0 = chunk*4;
        #pragma unroll
        for (int t = 0; t < 4; t++) {
            float xa = out[(tok0+t)*64 + lane];
            float xb = out[(tok0+t)*64 + lane + 32];
            float ss = xa*xa + xb*xb;
            #pragma unroll
            for (int o = 16; o; o >>= 1) ss += __shfl_xor_sync(~0u, ss, o);
            float rinv = rsqrtf(ss * (1.f/64.f) + 1e-5f);
            int tp = t >> 1, c = t & 1;
            hview[(tp*64 + lane)*2 + c]      = xa * rinv * fns[lane];
            hview[(tp*64 + lane + 32)*2 + c] = xb * rinv * fns[lane + 32];
        }
        __syncwarp();

        unsigned long long acc[2][8];
        #pragma unroll
        for (int tp = 0; tp < 2; tp++)
            #pragma unroll
            for (int r = 0; r < 8; r++) acc[tp][r] = 0ull;

        #pragma unroll 4
        for (int j = 0; j < 64; j += 2) {
            ulonglong2 h0 = *(const ulonglong2*)(htp + j);
            ulonglong2 h1 = *(const ulonglong2*)(htp + 64 + j);
            #pragma unroll
            for (int r = 0; r < 8; r++) {
                float2 wf = *(const float2*)(w1s + (lane + r*32)*66 + j);
                unsigned long long wx = pk2(wf.x, wf.x);
                unsigned long long wy = pk2(wf.y, wf.y);
                acc[0][r] = ffma2_(wx, h0.x, acc[0][r]);
                acc[0][r] = ffma2_(wy, h0.y, acc[0][r]);
                acc[1][r] = ffma2_(wx, h1.x, acc[1][r]);
                acc[1][r] = ffma2_(wy, h1.y, acc[1][r]);
            }
        }

        unsigned long long* gh = g_hid + (size_t)(tok0 >> 1) * HID_;
        #pragma unroll
        for (int r = 0; r < 8; r++) {
            int o = lane + r*32;
            float bb = b1s[o];
            #pragma unroll
            for (int tp = 0; tp < 2; tp++) {
                float2 v = upk2(acc[tp][r]);
                gh[tp*256 + o] = pk2(gelu_(v.x + bb), gelu_(v.y + bb));
            }
        }
        __syncwarp();
    }
}

// ============ kernel 4b: FFN GEMM2 + residual ============
__global__ void __launch_bounds__(256) ffn2_kernel(
    const float* __restrict__ w2, const float* __restrict__ b2,
    float* __restrict__ out)
{
    extern __shared__ float sm[];
    float* w2s = sm;                 // 64*258
    float* b2s = w2s + 16512;

    const int tid = threadIdx.x, lane = tid & 31, w = tid >> 5;

    for (int i = tid; i < E_*HID_; i += blockDim.x) {
        int e = i >> 8, o = i & 255;
        w2s[e*258 + o] = w2[i];
    }
    if (tid < 64) b2s[tid] = b2[tid];
    __syncthreads();

    const float* w2a = w2s + lane*258;
    const float* w2b = w2s + (lane + 32)*258;

    for (int chunk = blockIdx.x*8 + w; chunk < NT_/8; chunk += gridDim.x*8) {
        const int tok0 = chunk*8;
        const unsigned long long* gh = g_hid + (size_t)(tok0 >> 1) * HID_;

        unsigned long long a2[4][2];
        #pragma unroll
        for (int tp = 0; tp < 4; tp++) { a2[tp][0] = 0ull; a2[tp][1] = 0ull; }

        #pragma unroll 4
        for (int o = 0; o < 256; o += 2) {
            float2 wa = *(const float2*)(w2a + o);
            float2 wb = *(const float2*)(w2b + o);
            unsigned long long wax = pk2(wa.x, wa.x), way = pk2(wa.y, wa.y);
            unsigned long long wbx = pk2(wb.x, wb.x), wby = pk2(wb.y, wb.y);
            #pragma unroll
            for (int tp = 0; tp < 4; tp++) {
                ulonglong2 hh = *(const ulonglong2*)(gh + tp*256 + o);
                a2[tp][0] = ffma2_(wax, hh.x, a2[tp][0]);
                a2[tp][0] = ffma2_(way, hh.y, a2[tp][0]);
                a2[tp][1] = ffma2_(wbx, hh.x, a2[tp][1]);
                a2[tp][1] = ffma2_(wby, hh.y, a2[tp][1]);
            }
        }

        #pragma unroll
        for (int tp = 0; tp < 4; tp++) {
            float2 v0 = upk2(a2[tp][0]);
            float2 v1 = upk2(a2[tp][1]);
            int t0 = tok0 + 2*tp;
            out[t0*64 + lane]          += b2s[lane]      + v0.x;
            out[(t0+1)*64 + lane]      += b2s[lane]      + v0.y;
            out[t0*64 + lane + 32]     += b2s[lane + 32] + v1.x;
            out[(t0+1)*64 + lane + 32] += b2s[lane + 32] + v1.y;
        }
    }
}

// ============ launch ============
extern "C" void kernel_launch(void* const* d_in, const int* in_sizes, int n_in,
                              void* d_out, int out_size)
{
    const float* x     = (const float*)d_in[0];
    const float* maddr = (const float*)d_in[1];
    const float* mvals = (const float*)d_in[2];
    const float* anw   = (const float*)d_in[3];
    const float* wq    = (const float*)d_in[4];
    const float* wk    = (const float*)d_in[5];
    const float* wv    = (const float*)d_in[6];
    const float* wo    = (const float*)d_in[7];
    const float* mnw   = (const float*)d_in[8];
    const float* mq    = (const float*)d_in[9];
    const float* mo    = (const float*)d_in[10];
    const float* fnw   = (const float*)d_in[11];
    const float* w1    = (const float*)d_in[12];
    const float* b1    = (const float*)d_in[13];
    const float* w2    = (const float*)d_in[14];
    const float* b2    = (const float*)d_in[15];
    float* out = (float*)d_out;

    const int QKV_SMEM  = (3*4224 + 64) * 4 + 8*128*8;            // 59,136
    const int ATT_SMEM  = 32768 + 33024 + 4096;                   // 69,888
    const int MEM_SMEM  = (4160*2 + 2112 + 2080 + 64 + 8*96) * 4; // 53,376
    const int FFN1_SMEM = (16896 + 256 + 64) * 4 + 8*128*8;       // 77,056
    const int FFN2_SMEM = (16512 + 64) * 4;                       // 66,304

    cudaFuncSetAttribute(qkv_kernel, cudaFuncAttributeMaxDynamicSharedMemorySize, QKV_SMEM);
    cudaFuncSetAttribute(attn_kernel, cudaFuncAttributeMaxDynamicSharedMemorySize, ATT_SMEM);
    cudaFuncSetAttribute(mem_kernel, cudaFuncAttributeMaxDynamicSharedMemorySize, MEM_SMEM);
    cudaFuncSetAttribute(ffn1_kernel, cudaFuncAttributeMaxDynamicSharedMemorySize, FFN1_SMEM);
    cudaFuncSetAttribute(ffn2_kernel, cudaFuncAttributeMaxDynamicSharedMemorySize, FFN2_SMEM);

    qkv_kernel<<<296, 256, QKV_SMEM>>>(x, anw, wq, wk, wv);
    attn_kernel<<<1024, 128, ATT_SMEM>>>();
    mem_kernel<<<592, 256, MEM_SMEM>>>(x, mvals, maddr, mnw, wo, mq, mo, out);
    ffn1_kernel<<<296, 256, FFN1_SMEM>>>(fnw, w1, b1, out);
    ffn2_kernel<<<296, 256, FFN2_SMEM>>>(w2, b2, out);
}

// round 8
// speedup vs baseline: 2.1698x; 1.3230x over previous
#include <cuda_runtime.h>
#include <cuda_bf16.h>
#include <math.h>

#define B_  32
#define S_  1024
#define E_  64
#define H_  4
#define HD_ 16
#define HID_ 256
#define AD_ 32
#define NS_ 64
#define NT_ (B_*S_)
#define QSCALE (0.25f * 1.4426950408889634f)

__device__ __align__(16) __nv_bfloat16 g_qh[B_*H_*S_*HD_];  // [bh][s][d], pre-scaled
__device__ __align__(16) __nv_bfloat16 g_kh[B_*H_*S_*HD_];  // [bh][s][d]
__device__ __align__(16) __nv_bfloat16 g_vt[B_*H_*HD_*S_];  // [bh][d][s]
__device__ float g_o[B_*S_*E_];
__device__ __align__(16) __nv_bfloat16 g_hidb[(size_t)NT_*HID_];  // [tok][256] GELU out

__device__ __forceinline__ unsigned long long pk2(float lo, float hi) {
    unsigned long long r; asm("mov.b64 %0,{%1,%2};" : "=l"(r) : "f"(lo), "f"(hi)); return r;
}
__device__ __forceinline__ float2 upk2(unsigned long long v) {
    float2 f; asm("mov.b64 {%0,%1},%2;" : "=f"(f.x), "=f"(f.y) : "l"(v)); return f;
}
__device__ __forceinline__ unsigned long long ffma2_(unsigned long long a,
    unsigned long long b, unsigned long long c) {
    unsigned long long d;
    asm("fma.rn.f32x2 %0,%1,%2,%3;" : "=l"(d) : "l"(a), "l"(b), "l"(c)); return d;
}
__device__ __forceinline__ float gelu_(float v) {
    return 0.5f * v * (1.f + erff(v * 0.70710678118654752f));
}
__device__ __forceinline__ float ex2_(float x) {
    float y; asm("ex2.approx.f32 %0,%1;" : "=f"(y) : "f"(x)); return y;
}
__device__ __forceinline__ unsigned pbf_(float lo, float hi) {
    unsigned r; asm("cvt.rn.bf16x2.f32 %0,%1,%2;" : "=r"(r) : "f"(hi), "f"(lo)); return r;
}
__device__ __forceinline__ void mma16816(float& c0, float& c1, float& c2, float& c3,
    unsigned a0, unsigned a1, unsigned a2, unsigned a3, unsigned b0, unsigned b1) {
    asm volatile("mma.sync.aligned.m16n8k16.row.col.f32.bf16.bf16.f32 "
        "{%0,%1,%2,%3},{%4,%5,%6,%7},{%8,%9},{%0,%1,%2,%3};"
        : "+f"(c0), "+f"(c1), "+f"(c2), "+f"(c3)
        : "r"(a0), "r"(a1), "r"(a2), "r"(a3), "r"(b0), "r"(b1));
}

// ============ kernel 1: rmsnorm + QKV (bf16 out, V transposed) ============
__global__ void __launch_bounds__(256) qkv_kernel(
    const float* __restrict__ x, const float* __restrict__ nw,
    const float* __restrict__ wq, const float* __restrict__ wk,
    const float* __restrict__ wv)
{
    extern __shared__ float sm[];
    float* ws  = sm;                 // 3*64*66
    float* nws = ws + 3*4224;
    unsigned long long* htp_all = (unsigned long long*)(nws + 64);

    const int tid = threadIdx.x, lane = tid & 31, w = tid >> 5;

    for (int i = tid; i < 64*64; i += blockDim.x) {
        int e = i >> 6, j = i & 63;
        ws[0*4224 + e*66 + j] = wq[i];
        ws[1*4224 + e*66 + j] = wk[i];
        ws[2*4224 + e*66 + j] = wv[i];
    }
    if (tid < 64) nws[tid] = nw[tid];
    __syncthreads();

    unsigned long long* htp = htp_all + w*128;
    float* hview = (float*)htp;

    for (int chunk = blockIdx.x*8 + w; chunk < NT_/4; chunk += gridDim.x*8) {
        const int tok0 = chunk*4;
        #pragma unroll
        for (int t = 0; t < 4; t++) {
            float xa = x[(tok0+t)*64 + lane];
            float xb = x[(tok0+t)*64 + lane + 32];
            float ss = xa*xa + xb*xb;
            #pragma unroll
            for (int o = 16; o; o >>= 1) ss += __shfl_xor_sync(~0u, ss, o);
            float rinv = rsqrtf(ss * (1.f/64.f) + 1e-5f);
            int tp = t >> 1, c = t & 1;
            hview[(tp*64 + lane)*2 + c]      = xa * rinv * nws[lane];
            hview[(tp*64 + lane + 32)*2 + c] = xb * rinv * nws[lane + 32];
        }
        __syncwarp();

        unsigned long long acc[3][2][2];
        #pragma unroll
        for (int p = 0; p < 3; p++)
            #pragma unroll
            for (int r = 0; r < 2; r++) { acc[p][r][0] = 0ull; acc[p][r][1] = 0ull; }

        #pragma unroll 4
        for (int j = 0; j < 64; j += 2) {
            ulonglong2 h0 = *(const ulonglong2*)(htp + j);
            ulonglong2 h1 = *(const ulonglong2*)(htp + 64 + j);
            #pragma unroll
            for (int p = 0; p < 3; p++)
                #pragma unroll
                for (int r = 0; r < 2; r++) {
                    float2 wf = *(const float2*)(ws + p*4224 + (lane + r*32)*66 + j);
                    unsigned long long wx = pk2(wf.x, wf.x);
                    unsigned long long wy = pk2(wf.y, wf.y);
                    acc[p][r][0] = ffma2_(wx, h0.x, acc[p][r][0]);
                    acc[p][r][0] = ffma2_(wy, h0.y, acc[p][r][0]);
                    acc[p][r][1] = ffma2_(wx, h1.x, acc[p][r][1]);
                    acc[p][r][1] = ffma2_(wy, h1.y, acc[p][r][1]);
                }
        }

        const int b0 = tok0 >> 10, s0 = tok0 & 1023;
        #pragma unroll
        for (int r = 0; r < 2; r++) {
            int e = lane + r*32, hh = e >> 4, d = e & 15;
            size_t bhi = (size_t)(b0*H_ + hh);
            #pragma unroll
            for (int tp = 0; tp < 2; tp++) {
                int s = s0 + tp*2;
                float2 vq = upk2(acc[0][r][tp]);
                g_qh[(bhi*S_ + s  )*16 + d] = __float2bfloat16(vq.x * QSCALE);
                g_qh[(bhi*S_ + s+1)*16 + d] = __float2bfloat16(vq.y * QSCALE);
                float2 vk = upk2(acc[1][r][tp]);
                g_kh[(bhi*S_ + s  )*16 + d] = __float2bfloat16(vk.x);
                g_kh[(bhi*S_ + s+1)*16 + d] = __float2bfloat16(vk.y);
                float2 vv = upk2(acc[2][r][tp]);
                *(unsigned*)&g_vt[(bhi*16 + d)*S_ + s] = pbf_(vv.x, vv.y);
            }
        }
        __syncwarp();
    }
}

// ============ kernel 2: causal attention via bf16 HMMA ============
__global__ void __launch_bounds__(128, 3) attn_kernel()
{
    const int bidx = blockIdx.x;
    const int qt = 7 - (bidx >> 7);          // heavy tiles first
    const int bh = bidx & 127;
    const int nk = (qt + 1) * 128;
    const int qbase = qt * 128;

    extern __shared__ char smc[];
    __nv_bfloat16* Ks = (__nv_bfloat16*)smc;                    // [nk][16]
    __nv_bfloat16* Vt = (__nv_bfloat16*)(smc + 32768);          // [16][1032]
    __nv_bfloat16* Qs = (__nv_bfloat16*)(smc + 32768 + 33024);  // [128][16]

    const int tid = threadIdx.x, lane = tid & 31, w = tid >> 5;

    {
        const uint4* src = (const uint4*)(g_kh + (size_t)bh * S_ * 16);
        uint4* dst = (uint4*)Ks;
        for (int i = tid; i < nk*2; i += 128) dst[i] = src[i];
    }
    {
        const uint4* src = (const uint4*)(g_qh + ((size_t)bh * S_ + qbase) * 16);
        uint4* dst = (uint4*)Qs;
        dst[tid] = src[tid];
        dst[tid + 128] = src[tid + 128];
    }
    for (int d = w; d < 16; d += 4) {
        const uint4* src = (const uint4*)(g_vt + ((size_t)bh*16 + d) * S_);
        uint4* dst = (uint4*)(Vt + d * 1032);
        for (int i = lane; i < nk/8; i += 32) dst[i] = src[i];
    }
    __syncthreads();

    const int g = lane >> 2, tg = lane & 3;

    unsigned qa[2][4];
    #pragma unroll
    for (int mf = 0; mf < 2; mf++) {
        int rr = w*32 + mf*16 + g;
        qa[mf][0] = *(const unsigned*)&Qs[ rr     *16 + 2*tg    ];
        qa[mf][1] = *(const unsigned*)&Qs[(rr + 8)*16 + 2*tg    ];
        qa[mf][2] = *(const unsigned*)&Qs[ rr     *16 + 2*tg + 8];
        qa[mf][3] = *(const unsigned*)&Qs[(rr + 8)*16 + 2*tg + 8];
    }

    float o[2][2][4];
    #pragma unroll
    for (int mf = 0; mf < 2; mf++)
        #pragma unroll
        for (int dh = 0; dh < 2; dh++)
            o[mf][dh][0] = o[mf][dh][1] = o[mf][dh][2] = o[mf][dh][3] = 0.f;
    float lsum[2][2] = {{0.f,0.f},{0.f,0.f}};

    auto step = [&](int j0, bool MASK) {
        unsigned kb[2][2], vb[2][2];
        #pragma unroll
        for (int kh = 0; kh < 2; kh++) {
            const __nv_bfloat16* kr = Ks + (j0 + kh*8 + g)*16 + 2*tg;
            kb[kh][0] = *(const unsigned*)kr;
            kb[kh][1] = *(const unsigned*)(kr + 8);
        }
        #pragma unroll
        for (int dh = 0; dh < 2; dh++) {
            const __nv_bfloat16* vr = Vt + (dh*8 + g)*1032 + j0 + 2*tg;
            vb[dh][0] = *(const unsigned*)vr;
            vb[dh][1] = *(const unsigned*)(vr + 8);
        }
        #pragma unroll
        for (int mf = 0; mf < 2; mf++) {
            float c[2][4];
            #pragma unroll
            for (int kh = 0; kh < 2; kh++) {
                c[kh][0] = c[kh][1] = c[kh][2] = c[kh][3] = 0.f;
                mma16816(c[kh][0], c[kh][1], c[kh][2], c[kh][3],
                         qa[mf][0], qa[mf][1], qa[mf][2], qa[mf][3],
                         kb[kh][0], kb[kh][1]);
            }
            const int r0 = qbase + w*32 + mf*16 + g, r1 = r0 + 8;
            float p[2][4];
            #pragma unroll
            for (int kh = 0; kh < 2; kh++) {
                int k0 = j0 + kh*8 + 2*tg;
                p[kh][0] = (!MASK || k0     <= r0) ? ex2_(c[kh][0]) : 0.f;
                p[kh][1] = (!MASK || k0 + 1 <= r0) ? ex2_(c[kh][1]) : 0.f;
                p[kh][2] = (!MASK || k0     <= r1) ? ex2_(c[kh][2]) : 0.f;
                p[kh][3] = (!MASK || k0 + 1 <= r1) ? ex2_(c[kh][3]) : 0.f;
            }
            lsum[mf][0] += (p[0][0] + p[0][1]) + (p[1][0] + p[1][1]);
            lsum[mf][1] += (p[0][2] + p[0][3]) + (p[1][2] + p[1][3]);
            unsigned pa0 = pbf_(p[0][0], p[0][1]);
            unsigned pa1 = pbf_(p[0][2], p[0][3]);
            unsigned pa2 = pbf_(p[1][0], p[1][1]);
            unsigned pa3 = pbf_(p[1][2], p[1][3]);
            #pragma unroll
            for (int dh = 0; dh < 2; dh++)
                mma16816(o[mf][dh][0], o[mf][dh][1], o[mf][dh][2], o[mf][dh][3],
                         pa0, pa1, pa2, pa3, vb[dh][0], vb[dh][1]);
        }
    };

    for (int j0 = 0; j0 < qbase; j0 += 16) step(j0, false);
    const int wlast = qbase + w*32 + 31;
    for (int j0 = qbase; j0 < nk; j0 += 16) {
        if (j0 > wlast) break;
        step(j0, true);
    }

    const int b = bh >> 2, h = bh & 3;
    #pragma unroll
    for (int mf = 0; mf < 2; mf++) {
        float l0 = lsum[mf][0], l1 = lsum[mf][1];
        l0 += __shfl_xor_sync(~0u, l0, 1); l0 += __shfl_xor_sync(~0u, l0, 2);
        l1 += __shfl_xor_sync(~0u, l1, 1); l1 += __shfl_xor_sync(~0u, l1, 2);
        float i0 = 1.f / l0, i1 = 1.f / l1;
        int r0 = qbase + w*32 + mf*16 + g;
        float* b0p = g_o + ((size_t)(b*S_ + r0))*64 + h*16;
        float* b1p = b0p + 8*64;
        *(float2*)(b0p + 2*tg)     = make_float2(o[mf][0][0]*i0, o[mf][0][1]*i0);
        *(float2*)(b0p + 8 + 2*tg) = make_float2(o[mf][1][0]*i0, o[mf][1][1]*i0);
        *(float2*)(b1p + 2*tg)     = make_float2(o[mf][0][2]*i1, o[mf][0][3]*i1);
        *(float2*)(b1p + 8 + 2*tg) = make_float2(o[mf][1][2]*i1, o[mf][1][3]*i1);
    }
}

// ============ kernel 3: wo-proj + residual + memory read ============
__global__ void __launch_bounds__(256) mem_kernel(
    const float* __restrict__ x,     const float* __restrict__ mvals,
    const float* __restrict__ maddr, const float* __restrict__ mnw,
    const float* __restrict__ wo,    const float* __restrict__ mq,
    const float* __restrict__ mo,    float* __restrict__ out)
{
    extern __shared__ float sm[];
    float* woT  = sm;              // 64*65
    float* moT  = woT + 4160;
    float* mqT  = moT + 4160;      // 64*33
    float* aT   = mqT + 2112;      // 32*65
    float* mnws = aT + 2080;
    float* rows = mnws + 64;       // 8*96

    const int tid = threadIdx.x, lane = tid & 31, w = tid >> 5;

    for (int i = tid; i < 4096; i += blockDim.x) {
        int e = i >> 6, j = i & 63;
        woT[j*65 + e] = wo[i];
        moT[j*65 + e] = mo[i];
    }
    for (int i = tid; i < AD_*E_; i += blockDim.x) {
        int a = i >> 6, e = i & 63;
        mqT[e*33 + a] = mq[i];
    }
    if (tid < 64) mnws[tid] = mnw[tid];
    if (tid < 64) {
        float ssum = 0.f, v[32];
        #pragma unroll
        for (int a = 0; a < 32; a++) { v[a] = maddr[tid*32 + a]; ssum += v[a]*v[a]; }
        float rn = 1.f / fmaxf(sqrtf(ssum), 1e-12f);
        #pragma unroll
        for (int a = 0; a < 32; a++) aT[a*65 + tid] = v[a] * rn;
    }
    __syncthreads();

    float* hrow = rows + w*96;
    float* qrow = hrow + 64;

    for (int tok = blockIdx.x*8 + w; tok < NT_; tok += gridDim.x*8) {
        const int b = tok >> 10;
        hrow[lane]      = g_o[tok*64 + lane];
        hrow[lane + 32] = g_o[tok*64 + lane + 32];
        __syncwarp();
        float x1a = x[tok*64 + lane], x1b = x[tok*64 + lane + 32];
        {
            float s0 = 0.f, s1 = 0.f;
            #pragma unroll
            for (int j = 0; j < 64; j++) {
                float hv = hrow[j];
                s0 += hv * woT[j*65 + lane];
                s1 += hv * woT[j*65 + lane + 32];
            }
            x1a += s0; x1b += s1;
        }
        __syncwarp();
        float ss = x1a*x1a + x1b*x1b;
        #pragma unroll
        for (int o = 16; o; o >>= 1) ss += __shfl_xor_sync(~0u, ss, o);
        float rinv = rsqrtf(ss * (1.f/64.f) + 1e-5f);
        hrow[lane]      = x1a * rinv * mnws[lane];
        hrow[lane + 32] = x1b * rinv * mnws[lane + 32];
        __syncwarp();
        float qa = 0.f;
        #pragma unroll
        for (int e = 0; e < 64; e++) qa += hrow[e] * mqT[e*33 + lane];
        float qsm = qa*qa;
        #pragma unroll
        for (int o = 16; o; o >>= 1) qsm += __shfl_xor_sync(~0u, qsm, o);
        float rq = 1.f / fmaxf(sqrtf(qsm), 1e-12f);
        qrow[lane] = qa * rq;
        __syncwarp();
        float sc0 = 0.f, sc1 = 0.f;
        #pragma unroll
        for (int a = 0; a < 32; a++) {
            float qv = qrow[a];
            sc0 += qv * aT[a*65 + lane];
            sc1 += qv * aT[a*65 + lane + 32];
        }
        sc0 *= 4.f; sc1 *= 4.f;
        unsigned f0 = __float_as_uint(sc0);
        unsigned m0 = (f0 & 0x80000000u) ? ~f0 : (f0 | 0x80000000u);
        unsigned key0 = (m0 & 0xFFFFFFC0u) | (unsigned)(63 - lane);
        unsigned f1 = __float_as_uint(sc1);
        unsigned m1 = (f1 & 0x80000000u) ? ~f1 : (f1 | 0x80000000u);
        unsigned key1 = (m1 & 0xFFFFFFC0u) | (unsigned)(31 - lane);
        float tv[8]; int ti[8];
        #pragma unroll
        for (int k = 0; k < 8; k++) {
            unsigned loc = key0 > key1 ? key0 : key1;
            unsigned r = __reduce_max_sync(0xffffffffu, loc);
            int idx = 63 - (int)(r & 63u);
            float vsel = __shfl_sync(0xffffffffu, (idx >= 32) ? sc1 : sc0, idx & 31);
            tv[k] = vsel; ti[k] = idx;
            if (idx == lane)      key0 = 0u;
            if (idx == lane + 32) key1 = 0u;
        }
        float wsum = 0.f, wk8[8];
        #pragma unroll
        for (int k = 0; k < 8; k++) { wk8[k] = __expf(tv[k] - tv[0]); wsum += wk8[k]; }
        float winv = 1.f / wsum;
        const float* mb = mvals + b * NS_ * E_;
        float r0 = 0.f, r1 = 0.f;
        #pragma unroll
        for (int k = 0; k < 8; k++) {
            float wv = wk8[k] * winv;
            const float* mrow = mb + ti[k]*64;
            r0 += wv * mrow[lane];
            r1 += wv * mrow[lane + 32];
        }
        hrow[lane] = r0; hrow[lane + 32] = r1;
        __syncwarp();
        float o0 = 0.f, o1 = 0.f;
        #pragma unroll
        for (int j = 0; j < 64; j++) {
            float rv = hrow[j];
            o0 += rv * moT[j*65 + lane];
            o1 += rv * moT[j*65 + lane + 32];
        }
        out[tok*64 + lane]      = x1a + o0;
        out[tok*64 + lane + 32] = x1b + o1;
        __syncwarp();
    }
}

// ============ kernel 4a: FFN GEMM1 via HMMA + GELU -> g_hidb ============
// block = 128 tokens, 4 warps; warp = 32 tokens x 256 hidden in 4 N-chunks.
__global__ void __launch_bounds__(128, 3) ffn1_kernel(
    const float* __restrict__ fnw, const float* __restrict__ w1,
    const float* __restrict__ b1,  const float* __restrict__ out)
{
    extern __shared__ char smc[];
    __nv_bfloat16* w1s = (__nv_bfloat16*)smc;            // [256][72]
    __nv_bfloat16* As  = (__nv_bfloat16*)(smc + 36864);  // [128][72]
    float* b1s = (float*)(smc + 36864 + 18432);          // 256
    float* fns = b1s + 256;                              // 64

    const int tid = threadIdx.x, lane = tid & 31, w = tid >> 5;
    const int g = lane >> 2, tg = lane & 3;
    const int tok0 = blockIdx.x * 128;

    for (int i = tid; i < 256*64; i += 128) {
        int o = i >> 6, j = i & 63;
        w1s[o*72 + j] = __float2bfloat16(w1[i]);
    }
    b1s[tid] = b1[tid];
    b1s[tid + 128] = b1[tid + 128];
    if (tid < 64) fns[tid] = fnw[tid];
    __syncthreads();

    // rmsnorm: one token per thread -> bf16 A-tile
    {
        const float4* xr = (const float4*)(out + (size_t)(tok0 + tid)*64);
        float4 v[16];
        float ss = 0.f;
        #pragma unroll
        for (int i = 0; i < 16; i++) {
            v[i] = xr[i];
            ss += v[i].x*v[i].x + v[i].y*v[i].y + v[i].z*v[i].z + v[i].w*v[i].w;
        }
        float rinv = rsqrtf(ss * (1.f/64.f) + 1e-5f);
        #pragma unroll
        for (int i = 0; i < 16; i++) {
            *(unsigned*)&As[tid*72 + 4*i]     = pbf_(v[i].x*rinv*fns[4*i],   v[i].y*rinv*fns[4*i+1]);
            *(unsigned*)&As[tid*72 + 4*i + 2] = pbf_(v[i].z*rinv*fns[4*i+2], v[i].w*rinv*fns[4*i+3]);
        }
    }
    __syncthreads();

    // hoist A-frags for all 4 k-steps
    unsigned a[4][2][4];
    #pragma unroll
    for (int ks = 0; ks < 4; ks++)
        #pragma unroll
        for (int mf = 0; mf < 2; mf++) {
            int r = w*32 + mf*16 + g;
            int k = ks*16 + 2*tg;
            a[ks][mf][0] = *(const unsigned*)&As[ r      *72 + k];
            a[ks][mf][1] = *(const unsigned*)&As[(r + 8) *72 + k];
            a[ks][mf][2] = *(const unsigned*)&As[ r      *72 + k + 8];
            a[ks][mf][3] = *(const unsigned*)&As[(r + 8) *72 + k + 8];
        }

    #pragma unroll
    for (int ch = 0; ch < 4; ch++) {
        const int n0 = ch*64;
        float c[2][8][4];
        #pragma unroll
        for (int mf = 0; mf < 2; mf++)
            #pragma unroll
            for (int nf = 0; nf < 8; nf++)
                c[mf][nf][0] = c[mf][nf][1] = c[mf][nf][2] = c[mf][nf][3] = 0.f;

        #pragma unroll
        for (int ks = 0; ks < 4; ks++) {
            #pragma unroll
            for (int nf = 0; nf < 8; nf++) {
                const __nv_bfloat16* br = w1s + (n0 + nf*8 + g)*72 + ks*16 + 2*tg;
                unsigned b0 = *(const unsigned*)br;
                unsigned bq = *(const unsigned*)(br + 8);
                #pragma unroll
                for (int mf = 0; mf < 2; mf++)
                    mma16816(c[mf][nf][0], c[mf][nf][1], c[mf][nf][2], c[mf][nf][3],
                             a[ks][mf][0], a[ks][mf][1], a[ks][mf][2], a[ks][mf][3],
                             b0, bq);
            }
        }

        #pragma unroll
        for (int mf = 0; mf < 2; mf++) {
            const int r = tok0 + w*32 + mf*16 + g;
            #pragma unroll
            for (int nf = 0; nf < 8; nf++) {
                int e = n0 + nf*8 + 2*tg;
                float be0 = b1s[e], be1 = b1s[e+1];
                *(unsigned*)&g_hidb[(size_t)r*256 + e] =
                    pbf_(gelu_(c[mf][nf][0] + be0), gelu_(c[mf][nf][1] + be1));
                *(unsigned*)&g_hidb[(size_t)(r+8)*256 + e] =
                    pbf_(gelu_(c[mf][nf][2] + be0), gelu_(c[mf][nf][3] + be1));
            }
        }
    }
}

// ============ kernel 4b: FFN GEMM2 via HMMA + residual ============
__global__ void __launch_bounds__(128, 4) ffn2_kernel(
    const float* __restrict__ w2, const float* __restrict__ b2,
    float* __restrict__ out)
{
    extern __shared__ char smc[];
    __nv_bfloat16* w2s = (__nv_bfloat16*)smc;   // [64][264]
    float* b2s = (float*)(smc + 64*264*2);

    const int tid = threadIdx.x, lane = tid & 31, w = tid >> 5;
    const int g = lane >> 2, tg = lane & 3;
    const int tok0 = blockIdx.x * 128;

    for (int i = tid; i < 64*256; i += 128) {
        int e = i >> 8, o = i & 255;
        w2s[e*264 + o] = __float2bfloat16(w2[i]);
    }
    if (tid < 64) b2s[tid] = b2[tid];
    __syncthreads();

    float c[2][8][4];
    #pragma unroll
    for (int mf = 0; mf < 2; mf++)
        #pragma unroll
        for (int nf = 0; nf < 8; nf++)
            c[mf][nf][0] = c[mf][nf][1] = c[mf][nf][2] = c[mf][nf][3] = 0.f;

    const int m0 = tok0 + w*32;
    #pragma unroll 4
    for (int ks = 0; ks < 16; ks++) {
        const int k = ks*16 + 2*tg;
        unsigned a[2][4];
        #pragma unroll
        for (int mf = 0; mf < 2; mf++) {
            const __nv_bfloat16* ar = g_hidb + (size_t)(m0 + mf*16 + g)*256 + k;
            a[mf][0] = *(const unsigned*)ar;
            a[mf][1] = *(const unsigned*)(ar + 8*256);
            a[mf][2] = *(const unsigned*)(ar + 8);
            a[mf][3] = *(const unsigned*)(ar + 8*256 + 8);
        }
        #pragma unroll
        for (int nf = 0; nf < 8; nf++) {
            const __nv_bfloat16* br = w2s + (nf*8 + g)*264 + k;
            unsigned b0 = *(const unsigned*)br;
            unsigned bq = *(const unsigned*)(br + 8);
            #pragma unroll
            for (int mf = 0; mf < 2; mf++)
                mma16816(c[mf][nf][0], c[mf][nf][1], c[mf][nf][2], c[mf][nf][3],
                         a[mf][0], a[mf][1], a[mf][2], a[mf][3], b0, bq);
        }
    }

    #pragma unroll
    for (int mf = 0; mf < 2; mf++) {
        const int r = m0 + mf*16 + g;
        #pragma unroll
        for (int nf = 0; nf < 8; nf++) {
            int e = nf*8 + 2*tg;
            float2 o0 = *(float2*)&out[(size_t)r*64 + e];
            float2 o1 = *(float2*)&out[(size_t)(r+8)*64 + e];
            o0.x += b2s[e]   + c[mf][nf][0];
            o0.y += b2s[e+1] + c[mf][nf][1];
            o1.x += b2s[e]   + c[mf][nf][2];
            o1.y += b2s[e+1] + c[mf][nf][3];
            *(float2*)&out[(size_t)r*64 + e]     = o0;
            *(float2*)&out[(size_t)(r+8)*64 + e] = o1;
        }
    }
}

// ============ launch ============
extern "C" void kernel_launch(void* const* d_in, const int* in_sizes, int n_in,
                              void* d_out, int out_size)
{
    const float* x     = (const float*)d_in[0];
    const float* maddr = (const float*)d_in[1];
    const float* mvals = (const float*)d_in[2];
    const float* anw   = (const float*)d_in[3];
    const float* wq    = (const float*)d_in[4];
    const float* wk    = (const float*)d_in[5];
    const float* wv    = (const float*)d_in[6];
    const float* wo    = (const float*)d_in[7];
    const float* mnw   = (const float*)d_in[8];
    const float* mq    = (const float*)d_in[9];
    const float* mo    = (const float*)d_in[10];
    const float* fnw   = (const float*)d_in[11];
    const float* w1    = (const float*)d_in[12];
    const float* b1    = (const float*)d_in[13];
    const float* w2    = (const float*)d_in[14];
    const float* b2    = (const float*)d_in[15];
    float* out = (float*)d_out;

    const int QKV_SMEM  = (3*4224 + 64) * 4 + 8*128*8;            // 59,136
    const int ATT_SMEM  = 32768 + 33024 + 4096;                   // 69,888
    const int MEM_SMEM  = (4160*2 + 2112 + 2080 + 64 + 8*96) * 4; // 53,376
    const int FFN1_SMEM = 36864 + 18432 + (256 + 64) * 4;         // 56,576
    const int FFN2_SMEM = 64*264*2 + 64*4;                        // 34,048

    cudaFuncSetAttribute(qkv_kernel, cudaFuncAttributeMaxDynamicSharedMemorySize, QKV_SMEM);
    cudaFuncSetAttribute(attn_kernel, cudaFuncAttributeMaxDynamicSharedMemorySize, ATT_SMEM);
    cudaFuncSetAttribute(mem_kernel, cudaFuncAttributeMaxDynamicSharedMemorySize, MEM_SMEM);
    cudaFuncSetAttribute(ffn1_kernel, cudaFuncAttributeMaxDynamicSharedMemorySize, FFN1_SMEM);
    cudaFuncSetAttribute(ffn2_kernel, cudaFuncAttributeMaxDynamicSharedMemorySize, FFN2_SMEM);

    qkv_kernel<<<296, 256, QKV_SMEM>>>(x, anw, wq, wk, wv);
    attn_kernel<<<1024, 128, ATT_SMEM>>>();
    mem_kernel<<<592, 256, MEM_SMEM>>>(x, mvals, maddr, mnw, wo, mq, mo, out);
    ffn1_kernel<<<256, 128, FFN1_SMEM>>>(fnw, w1, b1, out);
    ffn2_kernel<<<256, 128, FFN2_SMEM>>>(w2, b2, out);
}

// round 9
// speedup vs baseline: 2.3319x; 1.0747x over previous
#include <cuda_runtime.h>
#include <cuda_bf16.h>
#include <math.h>

#define B_  32
#define S_  1024
#define E_  64
#define H_  4
#define HD_ 16
#define HID_ 256
#define AD_ 32
#define NS_ 64
#define NT_ (B_*S_)
#define QSCALE (0.25f * 1.4426950408889634f)

__device__ __align__(16) __nv_bfloat16 g_qh[B_*H_*S_*HD_];  // [bh][s][d], pre-scaled
__device__ __align__(16) __nv_bfloat16 g_kh[B_*H_*S_*HD_];  // [bh][s][d]
__device__ __align__(16) __nv_bfloat16 g_vt[B_*H_*HD_*S_];  // [bh][d][s]
__device__ float g_o[B_*S_*E_];
__device__ __align__(16) __nv_bfloat16 g_hidb[(size_t)NT_*HID_];  // [tok][256]
__device__ __align__(16) __nv_bfloat16 g_w1b[HID_*E_];
__device__ __align__(16) __nv_bfloat16 g_w2b[E_*HID_];

__device__ __forceinline__ unsigned long long pk2(float lo, float hi) {
    unsigned long long r; asm("mov.b64 %0,{%1,%2};" : "=l"(r) : "f"(lo), "f"(hi)); return r;
}
__device__ __forceinline__ float2 upk2(unsigned long long v) {
    float2 f; asm("mov.b64 {%0,%1},%2;" : "=f"(f.x), "=f"(f.y) : "l"(v)); return f;
}
__device__ __forceinline__ unsigned long long ffma2_(unsigned long long a,
    unsigned long long b, unsigned long long c) {
    unsigned long long d;
    asm("fma.rn.f32x2 %0,%1,%2,%3;" : "=l"(d) : "l"(a), "l"(b), "l"(c)); return d;
}
__device__ __forceinline__ float ex2_(float x) {
    float y; asm("ex2.approx.f32 %0,%1;" : "=f"(y) : "f"(x)); return y;
}
__device__ __forceinline__ float gelu_(float v) {
    // tanh-form GELU; activations here are |v| <~ 1 where this is ~exact
    float u = v * (0.7978845608f + 0.0356774081f * v * v);
    float e = ex2_(u * 2.885390082f);
    float r; asm("rcp.approx.f32 %0,%1;" : "=f"(r) : "f"(1.f + e));
    return 0.5f * v * (2.f - 2.f*r);
}
__device__ __forceinline__ unsigned pbf_(float lo, float hi) {
    unsigned r; asm("cvt.rn.bf16x2.f32 %0,%1,%2;" : "=r"(r) : "f"(hi), "f"(lo)); return r;
}
__device__ __forceinline__ void mma16816(float& c0, float& c1, float& c2, float& c3,
    unsigned a0, unsigned a1, unsigned a2, unsigned a3, unsigned b0, unsigned b1) {
    asm volatile("mma.sync.aligned.m16n8k16.row.col.f32.bf16.bf16.f32 "
        "{%0,%1,%2,%3},{%4,%5,%6,%7},{%8,%9},{%0,%1,%2,%3};"
        : "+f"(c0), "+f"(c1), "+f"(c2), "+f"(c3)
        : "r"(a0), "r"(a1), "r"(a2), "r"(a3), "r"(b0), "r"(b1));
}

// ============ kernel 0: pre-convert FFN weights to bf16 ============
__global__ void __launch_bounds__(256) cvt_kernel(
    const float* __restrict__ w1, const float* __restrict__ w2)
{
    int i = blockIdx.x*256 + threadIdx.x;
    if (i < HID_*E_) {
        g_w1b[i] = __float2bfloat16(w1[i]);
        g_w2b[i] = __float2bfloat16(w2[i]);
    }
}

// ============ kernel 1: rmsnorm + QKV (bf16 out, V transposed) ============
__global__ void __launch_bounds__(256) qkv_kernel(
    const float* __restrict__ x, const float* __restrict__ nw,
    const float* __restrict__ wq, const float* __restrict__ wk,
    const float* __restrict__ wv)
{
    extern __shared__ float sm[];
    float* ws  = sm;                 // 3*64*66
    float* nws = ws + 3*4224;
    unsigned long long* htp_all = (unsigned long long*)(nws + 64);

    const int tid = threadIdx.x, lane = tid & 31, w = tid >> 5;

    for (int i = tid; i < 64*64; i += blockDim.x) {
        int e = i >> 6, j = i & 63;
        ws[0*4224 + e*66 + j] = wq[i];
        ws[1*4224 + e*66 + j] = wk[i];
        ws[2*4224 + e*66 + j] = wv[i];
    }
    if (tid < 64) nws[tid] = nw[tid];
    __syncthreads();

    unsigned long long* htp = htp_all + w*128;
    float* hview = (float*)htp;

    for (int chunk = blockIdx.x*8 + w; chunk < NT_/4; chunk += gridDim.x*8) {
        const int tok0 = chunk*4;
        #pragma unroll
        for (int t = 0; t < 4; t++) {
            float xa = x[(tok0+t)*64 + lane];
            float xb = x[(tok0+t)*64 + lane + 32];
            float ss = xa*xa + xb*xb;
            #pragma unroll
            for (int o = 16; o; o >>= 1) ss += __shfl_xor_sync(~0u, ss, o);
            float rinv = rsqrtf(ss * (1.f/64.f) + 1e-5f);
            int tp = t >> 1, c = t & 1;
            hview[(tp*64 + lane)*2 + c]      = xa * rinv * nws[lane];
            hview[(tp*64 + lane + 32)*2 + c] = xb * rinv * nws[lane + 32];
        }
        __syncwarp();

        unsigned long long acc[3][2][2];
        #pragma unroll
        for (int p = 0; p < 3; p++)
            #pragma unroll
            for (int r = 0; r < 2; r++) { acc[p][r][0] = 0ull; acc[p][r][1] = 0ull; }

        #pragma unroll 4
        for (int j = 0; j < 64; j += 2) {
            ulonglong2 h0 = *(const ulonglong2*)(htp + j);
            ulonglong2 h1 = *(const ulonglong2*)(htp + 64 + j);
            #pragma unroll
            for (int p = 0; p < 3; p++)
                #pragma unroll
                for (int r = 0; r < 2; r++) {
                    float2 wf = *(const float2*)(ws + p*4224 + (lane + r*32)*66 + j);
                    unsigned long long wx = pk2(wf.x, wf.x);
                    unsigned long long wy = pk2(wf.y, wf.y);
                    acc[p][r][0] = ffma2_(wx, h0.x, acc[p][r][0]);
                    acc[p][r][0] = ffma2_(wy, h0.y, acc[p][r][0]);
                    acc[p][r][1] = ffma2_(wx, h1.x, acc[p][r][1]);
                    acc[p][r][1] = ffma2_(wy, h1.y, acc[p][r][1]);
                }
        }

        const int b0 = tok0 >> 10, s0 = tok0 & 1023;
        #pragma unroll
        for (int r = 0; r < 2; r++) {
            int e = lane + r*32, hh = e >> 4, d = e & 15;
            size_t bhi = (size_t)(b0*H_ + hh);
            #pragma unroll
            for (int tp = 0; tp < 2; tp++) {
                int s = s0 + tp*2;
                float2 vq = upk2(acc[0][r][tp]);
                g_qh[(bhi*S_ + s  )*16 + d] = __float2bfloat16(vq.x * QSCALE);
                g_qh[(bhi*S_ + s+1)*16 + d] = __float2bfloat16(vq.y * QSCALE);
                float2 vk = upk2(acc[1][r][tp]);
                g_kh[(bhi*S_ + s  )*16 + d] = __float2bfloat16(vk.x);
                g_kh[(bhi*S_ + s+1)*16 + d] = __float2bfloat16(vk.y);
                float2 vv = upk2(acc[2][r][tp]);
                *(unsigned*)&g_vt[(bhi*16 + d)*S_ + s] = pbf_(vv.x, vv.y);
            }
        }
        __syncwarp();
    }
}

// ============ kernel 2: causal attention via bf16 HMMA ============
__global__ void __launch_bounds__(128, 3) attn_kernel()
{
    const int bidx = blockIdx.x;
    const int qt = 7 - (bidx >> 7);          // heavy tiles first
    const int bh = bidx & 127;
    const int nk = (qt + 1) * 128;
    const int qbase = qt * 128;

    extern __shared__ char smc[];
    __nv_bfloat16* Ks = (__nv_bfloat16*)smc;                    // [nk][16]
    __nv_bfloat16* Vt = (__nv_bfloat16*)(smc + 32768);          // [16][1032]
    __nv_bfloat16* Qs = (__nv_bfloat16*)(smc + 32768 + 33024);  // [128][16]

    const int tid = threadIdx.x, lane = tid & 31, w = tid >> 5;

    {
        const uint4* src = (const uint4*)(g_kh + (size_t)bh * S_ * 16);
        uint4* dst = (uint4*)Ks;
        for (int i = tid; i < nk*2; i += 128) dst[i] = src[i];
    }
    {
        const uint4* src = (const uint4*)(g_qh + ((size_t)bh * S_ + qbase) * 16);
        uint4* dst = (uint4*)Qs;
        dst[tid] = src[tid];
        dst[tid + 128] = src[tid + 128];
    }
    for (int d = w; d < 16; d += 4) {
        const uint4* src = (const uint4*)(g_vt + ((size_t)bh*16 + d) * S_);
        uint4* dst = (uint4*)(Vt + d * 1032);
        for (int i = lane; i < nk/8; i += 32) dst[i] = src[i];
    }
    __syncthreads();

    const int g = lane >> 2, tg = lane & 3;

    unsigned qa[2][4];
    #pragma unroll
    for (int mf = 0; mf < 2; mf++) {
        int rr = w*32 + mf*16 + g;
        qa[mf][0] = *(const unsigned*)&Qs[ rr     *16 + 2*tg    ];
        qa[mf][1] = *(const unsigned*)&Qs[(rr + 8)*16 + 2*tg    ];
        qa[mf][2] = *(const unsigned*)&Qs[ rr     *16 + 2*tg + 8];
        qa[mf][3] = *(const unsigned*)&Qs[(rr + 8)*16 + 2*tg + 8];
    }

    float o[2][2][4];
    #pragma unroll
    for (int mf = 0; mf < 2; mf++)
        #pragma unroll
        for (int dh = 0; dh < 2; dh++)
            o[mf][dh][0] = o[mf][dh][1] = o[mf][dh][2] = o[mf][dh][3] = 0.f;
    float lsum[2][2] = {{0.f,0.f},{0.f,0.f}};

    auto step = [&](int j0, bool MASK) {
        unsigned kb[2][2], vb[2][2];
        #pragma unroll
        for (int kh = 0; kh < 2; kh++) {
            const __nv_bfloat16* kr = Ks + (j0 + kh*8 + g)*16 + 2*tg;
            kb[kh][0] = *(const unsigned*)kr;
            kb[kh][1] = *(const unsigned*)(kr + 8);
        }
        #pragma unroll
        for (int dh = 0; dh < 2; dh++) {
            const __nv_bfloat16* vr = Vt + (dh*8 + g)*1032 + j0 + 2*tg;
            vb[dh][0] = *(const unsigned*)vr;
            vb[dh][1] = *(const unsigned*)(vr + 8);
        }
        #pragma unroll
        for (int mf = 0; mf < 2; mf++) {
            float c[2][4];
            #pragma unroll
            for (int kh = 0; kh < 2; kh++) {
                c[kh][0] = c[kh][1] = c[kh][2] = c[kh][3] = 0.f;
                mma16816(c[kh][0], c[kh][1], c[kh][2], c[kh][3],
                         qa[mf][0], qa[mf][1], qa[mf][2], qa[mf][3],
                         kb[kh][0], kb[kh][1]);
            }
            const int r0 = qbase + w*32 + mf*16 + g, r1 = r0 + 8;
            float p[2][4];
            #pragma unroll
            for (int kh = 0; kh < 2; kh++) {
                int k0 = j0 + kh*8 + 2*tg;
                p[kh][0] = (!MASK || k0     <= r0) ? ex2_(c[kh][0]) : 0.f;
                p[kh][1] = (!MASK || k0 + 1 <= r0) ? ex2_(c[kh][1]) : 0.f;
                p[kh][2] = (!MASK || k0     <= r1) ? ex2_(c[kh][2]) : 0.f;
                p[kh][3] = (!MASK || k0 + 1 <= r1) ? ex2_(c[kh][3]) : 0.f;
            }
            lsum[mf][0] += (p[0][0] + p[0][1]) + (p[1][0] + p[1][1]);
            lsum[mf][1] += (p[0][2] + p[0][3]) + (p[1][2] + p[1][3]);
            unsigned pa0 = pbf_(p[0][0], p[0][1]);
            unsigned pa1 = pbf_(p[0][2], p[0][3]);
            unsigned pa2 = pbf_(p[1][0], p[1][1]);
            unsigned pa3 = pbf_(p[1][2], p[1][3]);
            #pragma unroll
            for (int dh = 0; dh < 2; dh++)
                mma16816(o[mf][dh][0], o[mf][dh][1], o[mf][dh][2], o[mf][dh][3],
                         pa0, pa1, pa2, pa3, vb[dh][0], vb[dh][1]);
        }
    };

    for (int j0 = 0; j0 < qbase; j0 += 16) step(j0, false);
    const int wlast = qbase + w*32 + 31;
    for (int j0 = qbase; j0 < nk; j0 += 16) {
        if (j0 > wlast) break;
        step(j0, true);
    }

    const int b = bh >> 2, h = bh & 3;
    #pragma unroll
    for (int mf = 0; mf < 2; mf++) {
        float l0 = lsum[mf][0], l1 = lsum[mf][1];
        l0 += __shfl_xor_sync(~0u, l0, 1); l0 += __shfl_xor_sync(~0u, l0, 2);
        l1 += __shfl_xor_sync(~0u, l1, 1); l1 += __shfl_xor_sync(~0u, l1, 2);
        float i0 = 1.f / l0, i1 = 1.f / l1;
        int r0 = qbase + w*32 + mf*16 + g;
        float* b0p = g_o + ((size_t)(b*S_ + r0))*64 + h*16;
        float* b1p = b0p + 8*64;
        *(float2*)(b0p + 2*tg)     = make_float2(o[mf][0][0]*i0, o[mf][0][1]*i0);
        *(float2*)(b0p + 8 + 2*tg) = make_float2(o[mf][1][0]*i0, o[mf][1][1]*i0);
        *(float2*)(b1p + 2*tg)     = make_float2(o[mf][0][2]*i1, o[mf][0][3]*i1);
        *(float2*)(b1p + 8 + 2*tg) = make_float2(o[mf][1][2]*i1, o[mf][1][3]*i1);
    }
}

// ============ kernel 3: wo-proj + residual + memory read ============
__global__ void __launch_bounds__(256) mem_kernel(
    const float* __restrict__ x,     const float* __restrict__ mvals,
    const float* __restrict__ maddr, const float* __restrict__ mnw,
    const float* __restrict__ wo,    const float* __restrict__ mq,
    const float* __restrict__ mo,    float* __restrict__ out)
{
    extern __shared__ float sm[];
    float* woT  = sm;              // 64*65
    float* moT  = woT + 4160;
    float* mqT  = moT + 4160;      // 64*33
    float* aT   = mqT + 2112;      // 32*65
    float* mnws = aT + 2080;
    float* rows = mnws + 64;       // 8*96

    const int tid = threadIdx.x, lane = tid & 31, w = tid >> 5;

    for (int i = tid; i < 4096; i += blockDim.x) {
        int e = i >> 6, j = i & 63;
        woT[j*65 + e] = wo[i];
        moT[j*65 + e] = mo[i];
    }
    for (int i = tid; i < AD_*E_; i += blockDim.x) {
        int a = i >> 6, e = i & 63;
        mqT[e*33 + a] = mq[i];
    }
    if (tid < 64) mnws[tid] = mnw[tid];
    if (tid < 64) {
        float ssum = 0.f, v[32];
        #pragma unroll
        for (int a = 0; a < 32; a++) { v[a] = maddr[tid*32 + a]; ssum += v[a]*v[a]; }
        float rn = 1.f / fmaxf(sqrtf(ssum), 1e-12f);
        #pragma unroll
        for (int a = 0; a < 32; a++) aT[a*65 + tid] = v[a] * rn;
    }
    __syncthreads();

    float* hrow = rows + w*96;
    float* qrow = hrow + 64;

    for (int tok = blockIdx.x*8 + w; tok < NT_; tok += gridDim.x*8) {
        const int b = tok >> 10;
        hrow[lane]      = g_o[tok*64 + lane];
        hrow[lane + 32] = g_o[tok*64 + lane + 32];
        __syncwarp();
        float x1a = x[tok*64 + lane], x1b = x[tok*64 + lane + 32];
        {
            float s0 = 0.f, s1 = 0.f;
            #pragma unroll
            for (int j = 0; j < 64; j++) {
                float hv = hrow[j];
                s0 += hv * woT[j*65 + lane];
                s1 += hv * woT[j*65 + lane + 32];
            }
            x1a += s0; x1b += s1;
        }
        __syncwarp();
        float ss = x1a*x1a + x1b*x1b;
        #pragma unroll
        for (int o = 16; o; o >>= 1) ss += __shfl_xor_sync(~0u, ss, o);
        float rinv = rsqrtf(ss * (1.f/64.f) + 1e-5f);
        hrow[lane]      = x1a * rinv * mnws[lane];
        hrow[lane + 32] = x1b * rinv * mnws[lane + 32];
        __syncwarp();
        float qa = 0.f;
        #pragma unroll
        for (int e = 0; e < 64; e++) qa += hrow[e] * mqT[e*33 + lane];
        float qsm = qa*qa;
        #pragma unroll
        for (int o = 16; o; o >>= 1) qsm += __shfl_xor_sync(~0u, qsm, o);
        float rq = 1.f / fmaxf(sqrtf(qsm), 1e-12f);
        qrow[lane] = qa * rq;
        __syncwarp();
        float sc0 = 0.f, sc1 = 0.f;
        #pragma unroll
        for (int a = 0; a < 32; a++) {
            float qv = qrow[a];
            sc0 += qv * aT[a*65 + lane];
            sc1 += qv * aT[a*65 + lane + 32];
        }
        sc0 *= 4.f; sc1 *= 4.f;
        unsigned f0 = __float_as_uint(sc0);
        unsigned m0 = (f0 & 0x80000000u) ? ~f0 : (f0 | 0x80000000u);
        unsigned key0 = (m0 & 0xFFFFFFC0u) | (unsigned)(63 - lane);
        unsigned f1 = __float_as_uint(sc1);
        unsigned m1 = (f1 & 0x80000000u) ? ~f1 : (f1 | 0x80000000u);
        unsigned key1 = (m1 & 0xFFFFFFC0u) | (unsigned)(31 - lane);
        float tv[8]; int ti[8];
        #pragma unroll
        for (int k = 0; k < 8; k++) {
            unsigned loc = key0 > key1 ? key0 : key1;
            unsigned r = __reduce_max_sync(0xffffffffu, loc);
            int idx = 63 - (int)(r & 63u);
            float vsel = __shfl_sync(0xffffffffu, (idx >= 32) ? sc1 : sc0, idx & 31);
            tv[k] = vsel; ti[k] = idx;
            if (idx == lane)      key0 = 0u;
            if (idx == lane + 32) key1 = 0u;
        }
        float wsum = 0.f, wk8[8];
        #pragma unroll
        for (int k = 0; k < 8; k++) { wk8[k] = __expf(tv[k] - tv[0]); wsum += wk8[k]; }
        float winv = 1.f / wsum;
        const float* mb = mvals + b * NS_ * E_;
        float r0 = 0.f, r1 = 0.f;
        #pragma unroll
        for (int k = 0; k < 8; k++) {
            float wv = wk8[k] * winv;
            const float* mrow = mb + ti[k]*64;
            r0 += wv * mrow[lane];
            r1 += wv * mrow[lane + 32];
        }
        hrow[lane] = r0; hrow[lane + 32] = r1;
        __syncwarp();
        float o0 = 0.f, o1 = 0.f;
        #pragma unroll
        for (int j = 0; j < 64; j++) {
            float rv = hrow[j];
            o0 += rv * moT[j*65 + lane];
            o1 += rv * moT[j*65 + lane + 32];
        }
        out[tok*64 + lane]      = x1a + o0;
        out[tok*64 + lane + 32] = x1b + o1;
        __syncwarp();
    }
}

// ============ kernel 4a: FFN GEMM1 via HMMA + fast GELU -> g_hidb ============
// block = 128 tokens, 8 warps: warp = (token-quarter, hidden-half) -> 32x128.
__global__ void __launch_bounds__(256, 2) ffn1_kernel(
    const float* __restrict__ fnw, const float* __restrict__ b1,
    const float* __restrict__ out)
{
    extern __shared__ char smc[];
    __nv_bfloat16* w1s = (__nv_bfloat16*)smc;            // [256][72]
    __nv_bfloat16* As  = (__nv_bfloat16*)(smc + 36864);  // [128][72]
    float* b1s = (float*)(smc + 36864 + 18432);          // 256
    float* fns = b1s + 256;                              // 64

    const int tid = threadIdx.x, lane = tid & 31, w = tid >> 5;
    const int g = lane >> 2, tg = lane & 3;
    const int wm = w & 3, nh = w >> 2;
    const int tok0 = blockIdx.x * 128;

    for (int i = tid; i < 256*32; i += 256) {
        int j2 = i*2;
        int o = j2 >> 6, j = j2 & 63;
        *(unsigned*)&w1s[o*72 + j] = ((const unsigned*)g_w1b)[i];
    }
    b1s[tid] = b1[tid];
    if (tid < 64) fns[tid] = fnw[tid];
    __syncthreads();

    if (tid < 128) {
        const float4* xr = (const float4*)(out + (size_t)(tok0 + tid)*64);
        float4 v[16];
        float ss = 0.f;
        #pragma unroll
        for (int i = 0; i < 16; i++) {
            v[i] = xr[i];
            ss += v[i].x*v[i].x + v[i].y*v[i].y + v[i].z*v[i].z + v[i].w*v[i].w;
        }
        float rinv = rsqrtf(ss * (1.f/64.f) + 1e-5f);
        #pragma unroll
        for (int i = 0; i < 16; i++) {
            *(unsigned*)&As[tid*72 + 4*i]     = pbf_(v[i].x*rinv*fns[4*i],   v[i].y*rinv*fns[4*i+1]);
            *(unsigned*)&As[tid*72 + 4*i + 2] = pbf_(v[i].z*rinv*fns[4*i+2], v[i].w*rinv*fns[4*i+3]);
        }
    }
    __syncthreads();

    unsigned a[4][2][4];
    #pragma unroll
    for (int ks = 0; ks < 4; ks++)
        #pragma unroll
        for (int mf = 0; mf < 2; mf++) {
            int r = wm*32 + mf*16 + g;
            int k = ks*16 + 2*tg;
            a[ks][mf][0] = *(const unsigned*)&As[ r      *72 + k];
            a[ks][mf][1] = *(const unsigned*)&As[(r + 8) *72 + k];
            a[ks][mf][2] = *(const unsigned*)&As[ r      *72 + k + 8];
            a[ks][mf][3] = *(const unsigned*)&As[(r + 8) *72 + k + 8];
        }

    #pragma unroll
    for (int ch = 0; ch < 2; ch++) {
        const int n0 = nh*128 + ch*64;
        float c[2][8][4];
        #pragma unroll
        for (int mf = 0; mf < 2; mf++)
            #pragma unroll
            for (int nf = 0; nf < 8; nf++)
                c[mf][nf][0] = c[mf][nf][1] = c[mf][nf][2] = c[mf][nf][3] = 0.f;

        #pragma unroll
        for (int ks = 0; ks < 4; ks++) {
            #pragma unroll
            for (int nf = 0; nf < 8; nf++) {
                const __nv_bfloat16* br = w1s + (n0 + nf*8 + g)*72 + ks*16 + 2*tg;
                unsigned b0 = *(const unsigned*)br;
                unsigned bq = *(const unsigned*)(br + 8);
                #pragma unroll
                for (int mf = 0; mf < 2; mf++)
                    mma16816(c[mf][nf][0], c[mf][nf][1], c[mf][nf][2], c[mf][nf][3],
                             a[ks][mf][0], a[ks][mf][1], a[ks][mf][2], a[ks][mf][3],
                             b0, bq);
            }
        }

        #pragma unroll
        for (int mf = 0; mf < 2; mf++) {
            const int r = tok0 + wm*32 + mf*16 + g;
            #pragma unroll
            for (int nf = 0; nf < 8; nf++) {
                int e = n0 + nf*8 + 2*tg;
                float be0 = b1s[e], be1 = b1s[e+1];
                *(unsigned*)&g_hidb[(size_t)r*256 + e] =
                    pbf_(gelu_(c[mf][nf][0] + be0), gelu_(c[mf][nf][1] + be1));
                *(unsigned*)&g_hidb[(size_t)(r+8)*256 + e] =
                    pbf_(gelu_(c[mf][nf][2] + be0), gelu_(c[mf][nf][3] + be1));
            }
        }
    }
}

// ============ kernel 4b: FFN GEMM2 via HMMA + residual ============
__global__ void __launch_bounds__(128, 4) ffn2_kernel(
    const float* __restrict__ b2, float* __restrict__ out)
{
    extern __shared__ char smc[];
    __nv_bfloat16* w2s = (__nv_bfloat16*)smc;   // [64][264]
    float* b2s = (float*)(smc + 64*264*2);

    const int tid = threadIdx.x, lane = tid & 31, w = tid >> 5;
    const int g = lane >> 2, tg = lane & 3;
    const int tok0 = blockIdx.x * 128;

    for (int i = tid; i < 64*128; i += 128) {
        int j2 = i*2;
        int e = j2 >> 8, o = j2 & 255;
        *(unsigned*)&w2s[e*264 + o] = ((const unsigned*)g_w2b)[i];
    }
    if (tid < 64) b2s[tid] = b2[tid];
    __syncthreads();

    float c[2][8][4];
    #pragma unroll
    for (int mf = 0; mf < 2; mf++)
        #pragma unroll
        for (int nf = 0; nf < 8; nf++)
            c[mf][nf][0] = c[mf][nf][1] = c[mf][nf][2] = c[mf][nf][3] = 0.f;

    const int m0 = tok0 + w*32;
    #pragma unroll 4
    for (int ks = 0; ks < 16; ks++) {
        const int k = ks*16 + 2*tg;
        unsigned a[2][4];
        #pragma unroll
        for (int mf = 0; mf < 2; mf++) {
            const __nv_bfloat16* ar = g_hidb + (size_t)(m0 + mf*16 + g)*256 + k;
            a[mf][0] = *(const unsigned*)ar;
            a[mf][1] = *(const unsigned*)(ar + 8*256);
            a[mf][2] = *(const unsigned*)(ar + 8);
            a[mf][3] = *(const unsigned*)(ar + 8*256 + 8);
        }
        #pragma unroll
        for (int nf = 0; nf < 8; nf++) {
            const __nv_bfloat16* br = w2s + (nf*8 + g)*264 + k;
            unsigned b0 = *(const unsigned*)br;
            unsigned bq = *(const unsigned*)(br + 8);
            #pragma unroll
            for (int mf = 0; mf < 2; mf++)
                mma16816(c[mf][nf][0], c[mf][nf][1], c[mf][nf][2], c[mf][nf][3],
                         a[mf][0], a[mf][1], a[mf][2], a[mf][3], b0, bq);
        }
    }

    #pragma unroll
    for (int mf = 0; mf < 2; mf++) {
        const int r = m0 + mf*16 + g;
        #pragma unroll
        for (int nf = 0; nf < 8; nf++) {
            int e = nf*8 + 2*tg;
            float2 o0 = *(float2*)&out[(size_t)r*64 + e];
            float2 o1 = *(float2*)&out[(size_t)(r+8)*64 + e];
            o0.x += b2s[e]   + c[mf][nf][0];
            o0.y += b2s[e+1] + c[mf][nf][1];
            o1.x += b2s[e]   + c[mf][nf][2];
            o1.y += b2s[e+1] + c[mf][nf][3];
            *(float2*)&out[(size_t)r*64 + e]     = o0;
            *(float2*)&out[(size_t)(r+8)*64 + e] = o1;
        }
    }
}

// ============ launch ============
extern "C" void kernel_launch(void* const* d_in, const int* in_sizes, int n_in,
                              void* d_out, int out_size)
{
    const float* x     = (const float*)d_in[0];
    const float* maddr = (const float*)d_in[1];
    const float* mvals = (const float*)d_in[2];
    const float* anw   = (const float*)d_in[3];
    const float* wq    = (const float*)d_in[4];
    const float* wk    = (const float*)d_in[5];
    const float* wv    = (const float*)d_in[6];
    const float* wo    = (const float*)d_in[7];
    const float* mnw   = (const float*)d_in[8];
    const float* mq    = (const float*)d_in[9];
    const float* mo    = (const float*)d_in[10];
    const float* fnw   = (const float*)d_in[11];
    const float* w1    = (const float*)d_in[12];
    const float* b1    = (const float*)d_in[13];
    const float* w2    = (const float*)d_in[14];
    const float* b2    = (const float*)d_in[15];
    float* out = (float*)d_out;

    const int QKV_SMEM  = (3*4224 + 64) * 4 + 8*128*8;            // 59,136
    const int ATT_SMEM  = 32768 + 33024 + 4096;                   // 69,888
    const int MEM_SMEM  = (4160*2 + 2112 + 2080 + 64 + 8*96) * 4; // 53,376
    const int FFN1_SMEM = 36864 + 18432 + (256 + 64) * 4;         // 56,576
    const int FFN2_SMEM = 64*264*2 + 64*4;                        // 34,048

    cudaFuncSetAttribute(qkv_kernel, cudaFuncAttributeMaxDynamicSharedMemorySize, QKV_SMEM);
    cudaFuncSetAttribute(attn_kernel, cudaFuncAttributeMaxDynamicSharedMemorySize, ATT_SMEM);
    cudaFuncSetAttribute(mem_kernel, cudaFuncAttributeMaxDynamicSharedMemorySize, MEM_SMEM);
    cudaFuncSetAttribute(ffn1_kernel, cudaFuncAttributeMaxDynamicSharedMemorySize, FFN1_SMEM);
    cudaFuncSetAttribute(ffn2_kernel, cudaFuncAttributeMaxDynamicSharedMemorySize, FFN2_SMEM);

    cvt_kernel<<<64, 256>>>(w1, w2);
    qkv_kernel<<<296, 256, QKV_SMEM>>>(x, anw, wq, wk, wv);
    attn_kernel<<<1024, 128, ATT_SMEM>>>();
    mem_kernel<<<592, 256, MEM_SMEM>>>(x, mvals, maddr, mnw, wo, mq, mo, out);
    ffn1_kernel<<<256, 256, FFN1_SMEM>>>(fnw, b1, out);
    ffn2_kernel<<<256, 128, FFN2_SMEM>>>(b2, out);
}

// round 11
// speedup vs baseline: 2.3737x; 1.0179x over previous
#include <cuda_runtime.h>
#include <cuda_bf16.h>
#include <math.h>

#define B_  32
#define S_  1024
#define E_  64
#define H_  4
#define HD_ 16
#define HID_ 256
#define AD_ 32
#define NS_ 64
#define NT_ (B_*S_)
#define QSCALE (0.25f * 1.4426950408889634f)

__device__ __align__(16) __nv_bfloat16 g_qh[B_*H_*S_*HD_];  // [bh][s][d], pre-scaled
__device__ __align__(16) __nv_bfloat16 g_kh[B_*H_*S_*HD_];  // [bh][s][d]
__device__ __align__(16) __nv_bfloat16 g_vt[B_*H_*HD_*S_];  // [bh][d][s]
__device__ float g_o[B_*S_*E_];
__device__ __align__(16) __nv_bfloat16 g_hidb[(size_t)NT_*HID_];  // [tok][256]
__device__ __align__(16) __nv_bfloat16 g_w1b[HID_*E_];
__device__ __align__(16) __nv_bfloat16 g_w2b[E_*HID_];
__device__ __align__(16) __nv_bfloat16 g_wob[E_*E_];
__device__ __align__(16) __nv_bfloat16 g_mob[E_*E_];

__device__ __forceinline__ unsigned long long pk2(float lo, float hi) {
    unsigned long long r; asm("mov.b64 %0,{%1,%2};" : "=l"(r) : "f"(lo), "f"(hi)); return r;
}
__device__ __forceinline__ float2 upk2(unsigned long long v) {
    float2 f; asm("mov.b64 {%0,%1},%2;" : "=f"(f.x), "=f"(f.y) : "l"(v)); return f;
}
__device__ __forceinline__ unsigned long long ffma2_(unsigned long long a,
    unsigned long long b, unsigned long long c) {
    unsigned long long d;
    asm("fma.rn.f32x2 %0,%1,%2,%3;" : "=l"(d) : "l"(a), "l"(b), "l"(c)); return d;
}
__device__ __forceinline__ float ex2_(float x) {
    float y; asm("ex2.approx.f32 %0,%1;" : "=f"(y) : "f"(x)); return y;
}
__device__ __forceinline__ float gelu_(float v) {
    float u = v * (0.7978845608f + 0.0356774081f * v * v);
    float e = ex2_(u * 2.885390082f);
    float r; asm("rcp.approx.f32 %0,%1;" : "=f"(r) : "f"(1.f + e));
    return 0.5f * v * (2.f - 2.f*r);
}
__device__ __forceinline__ unsigned pbf_(float lo, float hi) {
    unsigned r; asm("cvt.rn.bf16x2.f32 %0,%1,%2;" : "=r"(r) : "f"(hi), "f"(lo)); return r;
}
__device__ __forceinline__ void mma16816(float& c0, float& c1, float& c2, float& c3,
    unsigned a0, unsigned a1, unsigned a2, unsigned a3, unsigned b0, unsigned b1) {
    asm volatile("mma.sync.aligned.m16n8k16.row.col.f32.bf16.bf16.f32 "
        "{%0,%1,%2,%3},{%4,%5,%6,%7},{%8,%9},{%0,%1,%2,%3};"
        : "+f"(c0), "+f"(c1), "+f"(c2), "+f"(c3)
        : "r"(a0), "r"(a1), "r"(a2), "r"(a3), "r"(b0), "r"(b1));
}

// ============ kernel 0: pre-convert weights to bf16 ============
__global__ void __launch_bounds__(256) cvt_kernel(
    const float* __restrict__ w1, const float* __restrict__ w2,
    const float* __restrict__ wo, const float* __restrict__ mo)
{
    int i = blockIdx.x*256 + threadIdx.x;
    if (i < HID_*E_) {
        g_w1b[i] = __float2bfloat16(w1[i]);
        g_w2b[i] = __float2bfloat16(w2[i]);
    }
    if (i < E_*E_) {
        g_wob[i] = __float2bfloat16(wo[i]);
        g_mob[i] = __float2bfloat16(mo[i]);
    }
}

// ============ kernel 1: rmsnorm + QKV (bf16 out, V transposed) ============
__global__ void __launch_bounds__(256) qkv_kernel(
    const float* __restrict__ x, const float* __restrict__ nw,
    const float* __restrict__ wq, const float* __restrict__ wk,
    const float* __restrict__ wv)
{
    extern __shared__ float sm[];
    float* ws  = sm;                 // 3*64*66
    float* nws = ws + 3*4224;
    unsigned long long* htp_all = (unsigned long long*)(nws + 64);

    const int tid = threadIdx.x, lane = tid & 31, w = tid >> 5;

    for (int i = tid; i < 64*64; i += blockDim.x) {
        int e = i >> 6, j = i & 63;
        ws[0*4224 + e*66 + j] = wq[i];
        ws[1*4224 + e*66 + j] = wk[i];
        ws[2*4224 + e*66 + j] = wv[i];
    }
    if (tid < 64) nws[tid] = nw[tid];
    __syncthreads();

    unsigned long long* htp = htp_all + w*128;
    float* hview = (float*)htp;

    for (int chunk = blockIdx.x*8 + w; chunk < NT_/4; chunk += gridDim.x*8) {
        const int tok0 = chunk*4;
        #pragma unroll
        for (int t = 0; t < 4; t++) {
            float xa = x[(tok0+t)*64 + lane];
            float xb = x[(tok0+t)*64 + lane + 32];
            float ss = xa*xa + xb*xb;
            #pragma unroll
            for (int o = 16; o; o >>= 1) ss += __shfl_xor_sync(~0u, ss, o);
            float rinv = rsqrtf(ss * (1.f/64.f) + 1e-5f);
            int tp = t >> 1, c = t & 1;
            hview[(tp*64 + lane)*2 + c]      = xa * rinv * nws[lane];
            hview[(tp*64 + lane + 32)*2 + c] = xb * rinv * nws[lane + 32];
        }
        __syncwarp();

        unsigned long long acc[3][2][2];
        #pragma unroll
        for (int p = 0; p < 3; p++)
            #pragma unroll
            for (int r = 0; r < 2; r++) { acc[p][r][0] = 0ull; acc[p][r][1] = 0ull; }

        #pragma unroll 4
        for (int j = 0; j < 64; j += 2) {
            ulonglong2 h0 = *(const ulonglong2*)(htp + j);
            ulonglong2 h1 = *(const ulonglong2*)(htp + 64 + j);
            #pragma unroll
            for (int p = 0; p < 3; p++)
                #pragma unroll
                for (int r = 0; r < 2; r++) {
                    float2 wf = *(const float2*)(ws + p*4224 + (lane + r*32)*66 + j);
                    unsigned long long wx = pk2(wf.x, wf.x);
                    unsigned long long wy = pk2(wf.y, wf.y);
                    acc[p][r][0] = ffma2_(wx, h0.x, acc[p][r][0]);
                    acc[p][r][0] = ffma2_(wy, h0.y, acc[p][r][0]);
                    acc[p][r][1] = ffma2_(wx, h1.x, acc[p][r][1]);
                    acc[p][r][1] = ffma2_(wy, h1.y, acc[p][r][1]);
                }
        }

        const int b0 = tok0 >> 10, s0 = tok0 & 1023;
        #pragma unroll
        for (int r = 0; r < 2; r++) {
            int e = lane + r*32, hh = e >> 4, d = e & 15;
            size_t bhi = (size_t)(b0*H_ + hh);
            #pragma unroll
            for (int tp = 0; tp < 2; tp++) {
                int s = s0 + tp*2;
                float2 vq = upk2(acc[0][r][tp]);
                g_qh[(bhi*S_ + s  )*16 + d] = __float2bfloat16(vq.x * QSCALE);
                g_qh[(bhi*S_ + s+1)*16 + d] = __float2bfloat16(vq.y * QSCALE);
                float2 vk = upk2(acc[1][r][tp]);
                g_kh[(bhi*S_ + s  )*16 + d] = __float2bfloat16(vk.x);
                g_kh[(bhi*S_ + s+1)*16 + d] = __float2bfloat16(vk.y);
                float2 vv = upk2(acc[2][r][tp]);
                *(unsigned*)&g_vt[(bhi*16 + d)*S_ + s] = pbf_(vv.x, vv.y);
            }
        }
        __syncwarp();
    }
}

// ============ kernel 2: causal attention via bf16 HMMA ============
__global__ void __launch_bounds__(128, 3) attn_kernel()
{
    const int bidx = blockIdx.x;
    const int qt = 7 - (bidx >> 7);          // heavy tiles first
    const int bh = bidx & 127;
    const int nk = (qt + 1) * 128;
    const int qbase = qt * 128;

    extern __shared__ char smc[];
    __nv_bfloat16* Ks = (__nv_bfloat16*)smc;                    // [nk][16]
    __nv_bfloat16* Vt = (__nv_bfloat16*)(smc + 32768);          // [16][1032]
    __nv_bfloat16* Qs = (__nv_bfloat16*)(smc + 32768 + 33024);  // [128][16]

    const int tid = threadIdx.x, lane = tid & 31, w = tid >> 5;

    {
        const uint4* src = (const uint4*)(g_kh + (size_t)bh * S_ * 16);
        uint4* dst = (uint4*)Ks;
        for (int i = tid; i < nk*2; i += 128) dst[i] = src[i];
    }
    {
        const uint4* src = (const uint4*)(g_qh + ((size_t)bh * S_ + qbase) * 16);
        uint4* dst = (uint4*)Qs;
        dst[tid] = src[tid];
        dst[tid + 128] = src[tid + 128];
    }
    for (int d = w; d < 16; d += 4) {
        const uint4* src = (const uint4*)(g_vt + ((size_t)bh*16 + d) * S_);
        uint4* dst = (uint4*)(Vt + d * 1032);
        for (int i = lane; i < nk/8; i += 32) dst[i] = src[i];
    }
    __syncthreads();

    const int g = lane >> 2, tg = lane & 3;

    unsigned qa[2][4];
    #pragma unroll
    for (int mf = 0; mf < 2; mf++) {
        int rr = w*32 + mf*16 + g;
        qa[mf][0] = *(const unsigned*)&Qs[ rr     *16 + 2*tg    ];
        qa[mf][1] = *(const unsigned*)&Qs[(rr + 8)*16 + 2*tg    ];
        qa[mf][2] = *(const unsigned*)&Qs[ rr     *16 + 2*tg + 8];
        qa[mf][3] = *(const unsigned*)&Qs[(rr + 8)*16 + 2*tg + 8];
    }

    float o[2][2][4];
    #pragma unroll
    for (int mf = 0; mf < 2; mf++)
        #pragma unroll
        for (int dh = 0; dh < 2; dh++)
            o[mf][dh][0] = o[mf][dh][1] = o[mf][dh][2] = o[mf][dh][3] = 0.f;
    float lsum[2][2] = {{0.f,0.f},{0.f,0.f}};

    auto step = [&](int j0, bool MASK) {
        unsigned kb[2][2], vb[2][2];
        #pragma unroll
        for (int kh = 0; kh < 2; kh++) {
            const __nv_bfloat16* kr = Ks + (j0 + kh*8 + g)*16 + 2*tg;
            kb[kh][0] = *(const unsigned*)kr;
            kb[kh][1] = *(const unsigned*)(kr + 8);
        }
        #pragma unroll
        for (int dh = 0; dh < 2; dh++) {
            const __nv_bfloat16* vr = Vt + (dh*8 + g)*1032 + j0 + 2*tg;
            vb[dh][0] = *(const unsigned*)vr;
            vb[dh][1] = *(const unsigned*)(vr + 8);
        }
        #pragma unroll
        for (int mf = 0; mf < 2; mf++) {
            float c[2][4];
            #pragma unroll
            for (int kh = 0; kh < 2; kh++) {
                c[kh][0] = c[kh][1] = c[kh][2] = c[kh][3] = 0.f;
                mma16816(c[kh][0], c[kh][1], c[kh][2], c[kh][3],
                         qa[mf][0], qa[mf][1], qa[mf][2], qa[mf][3],
                         kb[kh][0], kb[kh][1]);
            }
            const int r0 = qbase + w*32 + mf*16 + g, r1 = r0 + 8;
            float p[2][4];
            #pragma unroll
            for (int kh = 0; kh < 2; kh++) {
                int k0 = j0 + kh*8 + 2*tg;
                p[kh][0] = (!MASK || k0     <= r0) ? ex2_(c[kh][0]) : 0.f;
                p[kh][1] = (!MASK || k0 + 1 <= r0) ? ex2_(c[kh][1]) : 0.f;
                p[kh][2] = (!MASK || k0     <= r1) ? ex2_(c[kh][2]) : 0.f;
                p[kh][3] = (!MASK || k0 + 1 <= r1) ? ex2_(c[kh][3]) : 0.f;
            }
            lsum[mf][0] += (p[0][0] + p[0][1]) + (p[1][0] + p[1][1]);
            lsum[mf][1] += (p[0][2] + p[0][3]) + (p[1][2] + p[1][3]);
            unsigned pa0 = pbf_(p[0][0], p[0][1]);
            unsigned pa1 = pbf_(p[0][2], p[0][3]);
            unsigned pa2 = pbf_(p[1][0], p[1][1]);
            unsigned pa3 = pbf_(p[1][2], p[1][3]);
            #pragma unroll
            for (int dh = 0; dh < 2; dh++)
                mma16816(o[mf][dh][0], o[mf][dh][1], o[mf][dh][2], o[mf][dh][3],
                         pa0, pa1, pa2, pa3, vb[dh][0], vb[dh][1]);
        }
    };

    for (int j0 = 0; j0 < qbase; j0 += 16) step(j0, false);
    const int wlast = qbase + w*32 + 31;
    for (int j0 = qbase; j0 < nk; j0 += 16) {
        if (j0 > wlast) break;
        step(j0, true);
    }

    const int b = bh >> 2, h = bh & 3;
    #pragma unroll
    for (int mf = 0; mf < 2; mf++) {
        float l0 = lsum[mf][0], l1 = lsum[mf][1];
        l0 += __shfl_xor_sync(~0u, l0, 1); l0 += __shfl_xor_sync(~0u, l0, 2);
        l1 += __shfl_xor_sync(~0u, l1, 1); l1 += __shfl_xor_sync(~0u, l1, 2);
        float i0 = 1.f / l0, i1 = 1.f / l1;
        int r0 = qbase + w*32 + mf*16 + g;
        float* b0p = g_o + ((size_t)(b*S_ + r0))*64 + h*16;
        float* b1p = b0p + 8*64;
        *(float2*)(b0p + 2*tg)     = make_float2(o[mf][0][0]*i0, o[mf][0][1]*i0);
        *(float2*)(b0p + 8 + 2*tg) = make_float2(o[mf][1][0]*i0, o[mf][1][1]*i0);
        *(float2*)(b1p + 2*tg)     = make_float2(o[mf][0][2]*i1, o[mf][0][3]*i1);
        *(float2*)(b1p + 8 + 2*tg) = make_float2(o[mf][1][2]*i1, o[mf][1][3]*i1);
    }
}

// ============ kernel 3: mem stage — HMMA wo/mo projections + fp32 selection ============
// block = 64 tokens, 4 warps; each warp owns 16 tokens end-to-end (no block syncs
// after table load). Score path (mq-proj, l2norm, scores, top-8) stays fp32.
__global__ void __launch_bounds__(128, 3) mem_kernel(
    const float* __restrict__ x,     const float* __restrict__ mvals,
    const float* __restrict__ maddr, const float* __restrict__ mnw,
    const float* __restrict__ mq,    float* __restrict__ out)
{
    extern __shared__ char smc[];
    __nv_bfloat16* woB = (__nv_bfloat16*)smc;            // [64][72]
    __nv_bfloat16* moB = (__nv_bfloat16*)(smc + 9216);   // [64][72]
    __nv_bfloat16* As  = (__nv_bfloat16*)(smc + 18432);  // [64][72]
    float* x1s  = (float*)(smc + 27648);                 // [64][65]
    float* mqT  = x1s + 64*65;                           // [64][33]
    float* aT   = mqT + 64*33;                           // [32][65]
    float* mnws = aT + 32*65;                            // 64
    float* rows = mnws + 64;                             // 4*96

    const int tid = threadIdx.x, lane = tid & 31, w = tid >> 5;
    const int g = lane >> 2, tg = lane & 3;
    const int tok0 = blockIdx.x * 64;

    for (int i = tid; i < 2048; i += 128) {
        int o = i >> 5, j = (i & 31)*2;
        *(unsigned*)&woB[o*72 + j] = ((const unsigned*)g_wob)[i];
        *(unsigned*)&moB[o*72 + j] = ((const unsigned*)g_mob)[i];
    }
    for (int i = tid; i < 2048; i += 128) {
        int a = i >> 6, e = i & 63;
        mqT[e*33 + a] = mq[i];
    }
    if (tid < 64) mnws[tid] = mnw[tid];
    if (tid < 64) {
        float ssum = 0.f, v[32];
        #pragma unroll
        for (int a = 0; a < 32; a++) { v[a] = maddr[tid*32 + a]; ssum += v[a]*v[a]; }
        float rn = 1.f / fmaxf(sqrtf(ssum), 1e-12f);
        #pragma unroll
        for (int a = 0; a < 32; a++) aT[a*65 + tid] = v[a] * rn;
    }
    __syncthreads();

    // ---- Phase A: own 16 tokens of g_o -> bf16 A tile ----
    {
        int tloc = w*16 + (lane >> 1);
        int half = (lane & 1) * 32;
        const float2* src = (const float2*)(g_o + (size_t)(tok0 + tloc)*64 + half);
        #pragma unroll
        for (int i = 0; i < 16; i++) {
            float2 v = src[i];
            *(unsigned*)&As[tloc*72 + half + 2*i] = pbf_(v.x, v.y);
        }
    }
    __syncwarp();

    // ---- Phase B: HMMA wo-proj; x1 = x + av@wo^T ----
    {
        unsigned a[4][4];
        #pragma unroll
        for (int ks = 0; ks < 4; ks++) {
            int r = w*16 + g, k = ks*16 + 2*tg;
            a[ks][0] = *(unsigned*)&As[ r     *72 + k];
            a[ks][1] = *(unsigned*)&As[(r + 8)*72 + k];
            a[ks][2] = *(unsigned*)&As[ r     *72 + k + 8];
            a[ks][3] = *(unsigned*)&As[(r + 8)*72 + k + 8];
        }
        #pragma unroll
        for (int nf = 0; nf < 8; nf++) {
            float c0 = 0.f, c1 = 0.f, c2 = 0.f, c3 = 0.f;
            #pragma unroll
            for (int ks = 0; ks < 4; ks++) {
                const __nv_bfloat16* br = woB + (nf*8 + g)*72 + ks*16 + 2*tg;
                mma16816(c0, c1, c2, c3, a[ks][0], a[ks][1], a[ks][2], a[ks][3],
                         *(const unsigned*)br, *(const unsigned*)(br + 8));
            }
            int e = nf*8 + 2*tg;
            int r0 = w*16 + g, r1 = r0 + 8;
            float2 xv0 = *(const float2*)&x[(size_t)(tok0 + r0)*64 + e];
            float2 xv1 = *(const float2*)&x[(size_t)(tok0 + r1)*64 + e];
            x1s[r0*65 + e]     = xv0.x + c0;
            x1s[r0*65 + e + 1] = xv0.y + c1;
            x1s[r1*65 + e]     = xv1.x + c2;
            x1s[r1*65 + e + 1] = xv1.y + c3;
        }
    }
    __syncwarp();

    // ---- Phase C: fp32 middle (rmsnorm, mq, l2norm, scores, top-8, gather) ----
    float* hrow = rows + w*96;
    float* qrow = hrow + 64;
    for (int t = 0; t < 16; t++) {
        const int tloc = w*16 + t, gt = tok0 + tloc, b = gt >> 10;
        float x1a = x1s[tloc*65 + lane], x1b = x1s[tloc*65 + lane + 32];
        float ss = x1a*x1a + x1b*x1b;
        #pragma unroll
        for (int o = 16; o; o >>= 1) ss += __shfl_xor_sync(~0u, ss, o);
        float rinv = rsqrtf(ss * (1.f/64.f) + 1e-5f);
        hrow[lane]      = x1a * rinv * mnws[lane];
        hrow[lane + 32] = x1b * rinv * mnws[lane + 32];
        __syncwarp();
        float qa = 0.f;
        #pragma unroll
        for (int e = 0; e < 64; e++) qa += hrow[e] * mqT[e*33 + lane];
        float qsm = qa*qa;
        #pragma unroll
        for (int o = 16; o; o >>= 1) qsm += __shfl_xor_sync(~0u, qsm, o);
        float rq = 1.f / fmaxf(sqrtf(qsm), 1e-12f);
        qrow[lane] = qa * rq;
        __syncwarp();
        float sc0 = 0.f, sc1 = 0.f;
        #pragma unroll
        for (int a = 0; a < 32; a++) {
            float qv = qrow[a];
            sc0 += qv * aT[a*65 + lane];
            sc1 += qv * aT[a*65 + lane + 32];
        }
        sc0 *= 4.f; sc1 *= 4.f;
        unsigned f0 = __float_as_uint(sc0);
        unsigned m0 = (f0 & 0x80000000u) ? ~f0 : (f0 | 0x80000000u);
        unsigned key0 = (m0 & 0xFFFFFFC0u) | (unsigned)(63 - lane);
        unsigned f1 = __float_as_uint(sc1);
        unsigned m1 = (f1 & 0x80000000u) ? ~f1 : (f1 | 0x80000000u);
        unsigned key1 = (m1 & 0xFFFFFFC0u) | (unsigned)(31 - lane);
        float tv[8]; int ti[8];
        #pragma unroll
        for (int k = 0; k < 8; k++) {
            unsigned loc = key0 > key1 ? key0 : key1;
            unsigned r = __reduce_max_sync(0xffffffffu, loc);
            int idx = 63 - (int)(r & 63u);
            float vsel = __shfl_sync(0xffffffffu, (idx >= 32) ? sc1 : sc0, idx & 31);
            tv[k] = vsel; ti[k] = idx;
            if (idx == lane)      key0 = 0u;
            if (idx == lane + 32) key1 = 0u;
        }
        float wsum = 0.f, wk8[8];
        #pragma unroll
        for (int k = 0; k < 8; k++) { wk8[k] = __expf(tv[k] - tv[0]); wsum += wk8[k]; }
        float winv = 1.f / wsum;
        const float* mb = mvals + b * NS_ * E_;
        float r0 = 0.f, r1 = 0.f;
        #pragma unroll
        for (int k = 0; k < 8; k++) {
            float wv = wk8[k] * winv;
            const float* mrow = mb + ti[k]*64;
            r0 += wv * mrow[lane];
            r1 += wv * mrow[lane + 32];
        }
        As[tloc*72 + lane]      = __float2bfloat16(r0);
        As[tloc*72 + lane + 32] = __float2bfloat16(r1);
        __syncwarp();
    }

    // ---- Phase D: HMMA mo-proj; out = x1 + read_vals@mo^T ----
    {
        unsigned a[4][4];
        #pragma unroll
        for (int ks = 0; ks < 4; ks++) {
            int r = w*16 + g, k = ks*16 + 2*tg;
            a[ks][0] = *(unsigned*)&As[ r     *72 + k];
            a[ks][1] = *(unsigned*)&As[(r + 8)*72 + k];
            a[ks][2] = *(unsigned*)&As[ r     *72 + k + 8];
            a[ks][3] = *(unsigned*)&As[(r + 8)*72 + k + 8];
        }
        #pragma unroll
        for (int nf = 0; nf < 8; nf++) {
            float c0 = 0.f, c1 = 0.f, c2 = 0.f, c3 = 0.f;
            #pragma unroll
            for (int ks = 0; ks < 4; ks++) {
                const __nv_bfloat16* br = moB + (nf*8 + g)*72 + ks*16 + 2*tg;
                mma16816(c0, c1, c2, c3, a[ks][0], a[ks][1], a[ks][2], a[ks][3],
                         *(const unsigned*)br, *(const unsigned*)(br + 8));
            }
            int e = nf*8 + 2*tg;
            int r0 = w*16 + g, r1 = r0 + 8;
            *(float2*)&out[(size_t)(tok0 + r0)*64 + e] =
                make_float2(x1s[r0*65 + e] + c0, x1s[r0*65 + e + 1] + c1);
            *(float2*)&out[(size_t)(tok0 + r1)*64 + e] =
                make_float2(x1s[r1*65 + e] + c2, x1s[r1*65 + e + 1] + c3);
        }
    }
}

// ============ kernel 4a: FFN GEMM1 via HMMA + fast GELU -> g_hidb ============
__global__ void __launch_bounds__(256, 2) ffn1_kernel(
    const float* __restrict__ fnw, const float* __restrict__ b1,
    const float* __restrict__ out)
{
    extern __shared__ char smc[];
    __nv_bfloat16* w1s = (__nv_bfloat16*)smc;            // [256][72]
    __nv_bfloat16* As  = (__nv_bfloat16*)(smc + 36864);  // [128][72]
    float* b1s = (float*)(smc + 36864 + 18432);          // 256
    float* fns = b1s + 256;                              // 64

    const int tid = threadIdx.x, lane = tid & 31, w = tid >> 5;
    const int g = lane >> 2, tg = lane & 3;
    const int wm = w & 3, nh = w >> 2;
    const int tok0 = blockIdx.x * 128;

    for (int i = tid; i < 256*32; i += 256) {
        int j2 = i*2;
        int o = j2 >> 6, j = j2 & 63;
        *(unsigned*)&w1s[o*72 + j] = ((const unsigned*)g_w1b)[i];
    }
    b1s[tid] = b1[tid];
    if (tid < 64) fns[tid] = fnw[tid];
    __syncthreads();

    if (tid < 128) {
        const float4* xr = (const float4*)(out + (size_t)(tok0 + tid)*64);
        float4 v[16];
        float ss = 0.f;
        #pragma unroll
        for (int i = 0; i < 16; i++) {
            v[i] = xr[i];
            ss += v[i].x*v[i].x + v[i].y*v[i].y + v[i].z*v[i].z + v[i].w*v[i].w;
        }
        float rinv = rsqrtf(ss * (1.f/64.f) + 1e-5f);
        #pragma unroll
        for (int i = 0; i < 16; i++) {
            *(unsigned*)&As[tid*72 + 4*i]     = pbf_(v[i].x*rinv*fns[4*i],   v[i].y*rinv*fns[4*i+1]);
            *(unsigned*)&As[tid*72 + 4*i + 2] = pbf_(v[i].z*rinv*fns[4*i+2], v[i].w*rinv*fns[4*i+3]);
        }
    }
    __syncthreads();

    unsigned a[4][2][4];
    #pragma unroll
    for (int ks = 0; ks < 4; ks++)
        #pragma unroll
        for (int mf = 0; mf < 2; mf++) {
            int r = wm*32 + mf*16 + g;
            int k = ks*16 + 2*tg;
            a[ks][mf][0] = *(const unsigned*)&As[ r      *72 + k];
            a[ks][mf][1] = *(const unsigned*)&As[(r + 8) *72 + k];
            a[ks][mf][2] = *(const unsigned*)&As[ r      *72 + k + 8];
            a[ks][mf][3] = *(const unsigned*)&As[(r + 8) *72 + k + 8];
        }

    #pragma unroll
    for (int ch = 0; ch < 2; ch++) {
        const int n0 = nh*128 + ch*64;
        float c[2][8][4];
        #pragma unroll
        for (int mf = 0; mf < 2; mf++)
            #pragma unroll
            for (int nf = 0; nf < 8; nf++)
                c[mf][nf][0] = c[mf][nf][1] = c[mf][nf][2] = c[mf][nf][3] = 0.f;

        #pragma unroll
        for (int ks = 0; ks < 4; ks++) {
            #pragma unroll
            for (int nf = 0; nf < 8; nf++) {
                const __nv_bfloat16* br = w1s + (n0 + nf*8 + g)*72 + ks*16 + 2*tg;
                unsigned b0 = *(const unsigned*)br;
                unsigned bq = *(const unsigned*)(br + 8);
                #pragma unroll
                for (int mf = 0; mf < 2; mf++)
                    mma16816(c[mf][nf][0], c[mf][nf][1], c[mf][nf][2], c[mf][nf][3],
                             a[ks][mf][0], a[ks][mf][1], a[ks][mf][2], a[ks][mf][3],
                             b0, bq);
            }
        }

        #pragma unroll
        for (int mf = 0; mf < 2; mf++) {
            const int r = tok0 + wm*32 + mf*16 + g;
            #pragma unroll
            for (int nf = 0; nf < 8; nf++) {
                int e = n0 + nf*8 + 2*tg;
                float be0 = b1s[e], be1 = b1s[e+1];
                *(unsigned*)&g_hidb[(size_t)r*256 + e] =
                    pbf_(gelu_(c[mf][nf][0] + be0), gelu_(c[mf][nf][1] + be1));
                *(unsigned*)&g_hidb[(size_t)(r+8)*256 + e] =
                    pbf_(gelu_(c[mf][nf][2] + be0), gelu_(c[mf][nf][3] + be1));
            }
        }
    }
}

// ============ kernel 4b: FFN GEMM2 via HMMA + residual ============
__global__ void __launch_bounds__(128, 4) ffn2_kernel(
    const float* __restrict__ b2, float* __restrict__ out)
{
    extern __shared__ char smc[];
    __nv_bfloat16* w2s = (__nv_bfloat16*)smc;   // [64][264]
    float* b2s = (float*)(smc + 64*264*2);

    const int tid = threadIdx.x, lane = tid & 31, w = tid >> 5;
    const int g = lane >> 2, tg = lane & 3;
    const int tok0 = blockIdx.x * 128;

    for (int i = tid; i < 64*128; i += 128) {
        int j2 = i*2;
        int e = j2 >> 8, o = j2 & 255;
        *(unsigned*)&w2s[e*264 + o] = ((const unsigned*)g_w2b)[i];
    }
    if (tid < 64) b2s[tid] = b2[tid];
    __syncthreads();

    float c[2][8][4];
    #pragma unroll
    for (int mf = 0; mf < 2; mf++)
        #pragma unroll
        for (int nf = 0; nf < 8; nf++)
            c[mf][nf][0] = c[mf][nf][1] = c[mf][nf][2] = c[mf][nf][3] = 0.f;

    const int m0 = tok0 + w*32;
    #pragma unroll 4
    for (int ks = 0; ks < 16; ks++) {
        const int k = ks*16 + 2*tg;
        unsigned a[2][4];
        #pragma unroll
        for (int mf = 0; mf < 2; mf++) {
            const __nv_bfloat16* ar = g_hidb + (size_t)(m0 + mf*16 + g)*256 + k;
            a[mf][0] = *(const unsigned*)ar;
            a[mf][1] = *(const unsigned*)(ar + 8*256);
            a[mf][2] = *(const unsigned*)(ar + 8);
            a[mf][3] = *(const unsigned*)(ar + 8*256 + 8);
        }
        #pragma unroll
        for (int nf = 0; nf < 8; nf++) {
            const __nv_bfloat16* br = w2s + (nf*8 + g)*264 + k;
            unsigned b0 = *(const unsigned*)br;
            unsigned bq = *(const unsigned*)(br + 8);
            #pragma unroll
            for (int mf = 0; mf < 2; mf++)
                mma16816(c[mf][nf][0], c[mf][nf][1], c[mf][nf][2], c[mf][nf][3],
                         a[mf][0], a[mf][1], a[mf][2], a[mf][3], b0, bq);
        }
    }

    #pragma unroll
    for (int mf = 0; mf < 2; mf++) {
        const int r = m0 + mf*16 + g;
        #pragma unroll
        for (int nf = 0; nf < 8; nf++) {
            int e = nf*8 + 2*tg;
            float2 o0 = *(float2*)&out[(size_t)r*64 + e];
            float2 o1 = *(float2*)&out[(size_t)(r+8)*64 + e];
            o0.x += b2s[e]   + c[mf][nf][0];
            o0.y += b2s[e+1] + c[mf][nf][1];
            o1.x += b2s[e]   + c[mf][nf][2];
            o1.y += b2s[e+1] + c[mf][nf][3];
            *(float2*)&out[(size_t)r*64 + e]     = o0;
            *(float2*)&out[(size_t)(r+8)*64 + e] = o1;
        }
    }
}

// ============ launch ============
extern "C" void kernel_launch(void* const* d_in, const int* in_sizes, int n_in,
                              void* d_out, int out_size)
{
    const float* x     = (const float*)d_in[0];
    const float* maddr = (const float*)d_in[1];
    const float* mvals = (const float*)d_in[2];
    const float* anw   = (const float*)d_in[3];
    const float* wq    = (const float*)d_in[4];
    const float* wk    = (const float*)d_in[5];
    const float* wv    = (const float*)d_in[6];
    const float* wo    = (const float*)d_in[7];
    const float* mnw   = (const float*)d_in[8];
    const float* mq    = (const float*)d_in[9];
    const float* mo    = (const float*)d_in[10];
    const float* fnw   = (const float*)d_in[11];
    const float* w1    = (const float*)d_in[12];
    const float* b1    = (const float*)d_in[13];
    const float* w2    = (const float*)d_in[14];
    const float* b2    = (const float*)d_in[15];
    float* out = (float*)d_out;

    const int QKV_SMEM  = (3*4224 + 64) * 4 + 8*128*8;            // 59,136
    const int ATT_SMEM  = 32768 + 33024 + 4096;                   // 69,888
    const int MEM_SMEM  = 27648 + (64*65 + 64*33 + 32*65 + 64 + 4*96) * 4;  // 62,848
    const int FFN1_SMEM = 36864 + 18432 + (256 + 64) * 4;         // 56,576
    const int FFN2_SMEM = 64*264*2 + 64*4;                        // 34,048

    cudaFuncSetAttribute(qkv_kernel, cudaFuncAttributeMaxDynamicSharedMemorySize, QKV_SMEM);
    cudaFuncSetAttribute(attn_kernel, cudaFuncAttributeMaxDynamicSharedMemorySize, ATT_SMEM);
    cudaFuncSetAttribute(mem_kernel, cudaFuncAttributeMaxDynamicSharedMemorySize, MEM_SMEM);
    cudaFuncSetAttribute(ffn1_kernel, cudaFuncAttributeMaxDynamicSharedMemorySize, FFN1_SMEM);
    cudaFuncSetAttribute(ffn2_kernel, cudaFuncAttributeMaxDynamicSharedMemorySize, FFN2_SMEM);

    cvt_kernel<<<64, 256>>>(w1, w2, wo, mo);
    qkv_kernel<<<296, 256, QKV_SMEM>>>(x, anw, wq, wk, wv);
    attn_kernel<<<1024, 128, ATT_SMEM>>>();
    mem_kernel<<<512, 128, MEM_SMEM>>>(x, mvals, maddr, mnw, mq, out);
    ffn1_kernel<<<256, 256, FFN1_SMEM>>>(fnw, b1, out);
    ffn2_kernel<<<256, 128, FFN2_SMEM>>>(b2, out);
}

// round 13
// speedup vs baseline: 2.6240x; 1.1055x over previous
#include <cuda_runtime.h>
#include <cuda_bf16.h>
#include <math.h>

#define B_  32
#define S_  1024
#define E_  64
#define H_  4
#define HD_ 16
#define HID_ 256
#define AD_ 32
#define NS_ 64
#define NT_ (B_*S_)
#define QSCALE (0.25f * 1.4426950408889634f)

__device__ __align__(16) __nv_bfloat16 g_qh[B_*H_*S_*HD_];
__device__ __align__(16) __nv_bfloat16 g_kh[B_*H_*S_*HD_];
__device__ __align__(16) __nv_bfloat16 g_vt[B_*H_*HD_*S_];
__device__ float g_o[B_*S_*E_];
__device__ __align__(16) __nv_bfloat16 g_rv[(size_t)NT_*E_];      // read_vals bf16
__device__ __align__(16) __nv_bfloat16 g_hidb[(size_t)NT_*HID_];
__device__ __align__(16) __nv_bfloat16 g_w1b[HID_*E_];
__device__ __align__(16) __nv_bfloat16 g_w2b[E_*HID_];
__device__ __align__(16) __nv_bfloat16 g_wob[E_*E_];
__device__ __align__(16) __nv_bfloat16 g_mob[E_*E_];

__device__ __forceinline__ unsigned long long pk2(float lo, float hi) {
    unsigned long long r; asm("mov.b64 %0,{%1,%2};" : "=l"(r) : "f"(lo), "f"(hi)); return r;
}
__device__ __forceinline__ float2 upk2(unsigned long long v) {
    float2 f; asm("mov.b64 {%0,%1},%2;" : "=f"(f.x), "=f"(f.y) : "l"(v)); return f;
}
__device__ __forceinline__ unsigned long long ffma2_(unsigned long long a,
    unsigned long long b, unsigned long long c) {
    unsigned long long d;
    asm("fma.rn.f32x2 %0,%1,%2,%3;" : "=l"(d) : "l"(a), "l"(b), "l"(c)); return d;
}
__device__ __forceinline__ float ex2_(float x) {
    float y; asm("ex2.approx.f32 %0,%1;" : "=f"(y) : "f"(x)); return y;
}
__device__ __forceinline__ float gelu_(float v) {
    float u = v * (0.7978845608f + 0.0356774081f * v * v);
    float e = ex2_(u * 2.885390082f);
    float r; asm("rcp.approx.f32 %0,%1;" : "=f"(r) : "f"(1.f + e));
    return 0.5f * v * (2.f - 2.f*r);
}
__device__ __forceinline__ unsigned pbf_(float lo, float hi) {
    unsigned r; asm("cvt.rn.bf16x2.f32 %0,%1,%2;" : "=r"(r) : "f"(hi), "f"(lo)); return r;
}
__device__ __forceinline__ void mma16816(float& c0, float& c1, float& c2, float& c3,
    unsigned a0, unsigned a1, unsigned a2, unsigned a3, unsigned b0, unsigned b1) {
    asm volatile("mma.sync.aligned.m16n8k16.row.col.f32.bf16.bf16.f32 "
        "{%0,%1,%2,%3},{%4,%5,%6,%7},{%8,%9},{%0,%1,%2,%3};"
        : "+f"(c0), "+f"(c1), "+f"(c2), "+f"(c3)
        : "r"(a0), "r"(a1), "r"(a2), "r"(a3), "r"(b0), "r"(b1));
}

// ============ kernel 0: pre-convert weights to bf16 ============
__global__ void __launch_bounds__(256) cvt_kernel(
    const float* __restrict__ w1, const float* __restrict__ w2,
    const float* __restrict__ wo, const float* __restrict__ mo)
{
    int i = blockIdx.x*256 + threadIdx.x;
    if (i < HID_*E_) {
        g_w1b[i] = __float2bfloat16(w1[i]);
        g_w2b[i] = __float2bfloat16(w2[i]);
    }
    if (i < E_*E_) {
        g_wob[i] = __float2bfloat16(wo[i]);
        g_mob[i] = __float2bfloat16(mo[i]);
    }
}

// ============ kernel 1: rmsnorm + QKV (bf16 out, V transposed) ============
__global__ void __launch_bounds__(256) qkv_kernel(
    const float* __restrict__ x, const float* __restrict__ nw,
    const float* __restrict__ wq, const float* __restrict__ wk,
    const float* __restrict__ wv)
{
    extern __shared__ float sm[];
    float* ws  = sm;                 // 3*64*66
    float* nws = ws + 3*4224;
    unsigned long long* htp_all = (unsigned long long*)(nws + 64);

    const int tid = threadIdx.x, lane = tid & 31, w = tid >> 5;

    for (int i = tid; i < 64*64; i += blockDim.x) {
        int e = i >> 6, j = i & 63;
        ws[0*4224 + e*66 + j] = wq[i];
        ws[1*4224 + e*66 + j] = wk[i];
        ws[2*4224 + e*66 + j] = wv[i];
    }
    if (tid < 64) nws[tid] = nw[tid];
    __syncthreads();

    unsigned long long* htp = htp_all + w*128;
    float* hview = (float*)htp;

    for (int chunk = blockIdx.x*8 + w; chunk < NT_/4; chunk += gridDim.x*8) {
        const int tok0 = chunk*4;
        #pragma unroll
        for (int t = 0; t < 4; t++) {
            float xa = x[(tok0+t)*64 + lane];
            float xb = x[(tok0+t)*64 + lane + 32];
            float ss = xa*xa + xb*xb;
            #pragma unroll
            for (int o = 16; o; o >>= 1) ss += __shfl_xor_sync(~0u, ss, o);
            float rinv = rsqrtf(ss * (1.f/64.f) + 1e-5f);
            int tp = t >> 1, c = t & 1;
            hview[(tp*64 + lane)*2 + c]      = xa * rinv * nws[lane];
            hview[(tp*64 + lane + 32)*2 + c] = xb * rinv * nws[lane + 32];
        }
        __syncwarp();

        unsigned long long acc[3][2][2];
        #pragma unroll
        for (int p = 0; p < 3; p++)
            #pragma unroll
            for (int r = 0; r < 2; r++) { acc[p][r][0] = 0ull; acc[p][r][1] = 0ull; }

        #pragma unroll 4
        for (int j = 0; j < 64; j += 2) {
            ulonglong2 h0 = *(const ulonglong2*)(htp + j);
            ulonglong2 h1 = *(const ulonglong2*)(htp + 64 + j);
            #pragma unroll
            for (int p = 0; p < 3; p++)
                #pragma unroll
                for (int r = 0; r < 2; r++) {
                    float2 wf = *(const float2*)(ws + p*4224 + (lane + r*32)*66 + j);
                    unsigned long long wx = pk2(wf.x, wf.x);
                    unsigned long long wy = pk2(wf.y, wf.y);
                    acc[p][r][0] = ffma2_(wx, h0.x, acc[p][r][0]);
                    acc[p][r][0] = ffma2_(wy, h0.y, acc[p][r][0]);
                    acc[p][r][1] = ffma2_(wx, h1.x, acc[p][r][1]);
                    acc[p][r][1] = ffma2_(wy, h1.y, acc[p][r][1]);
                }
        }

        const int b0 = tok0 >> 10, s0 = tok0 & 1023;
        #pragma unroll
        for (int r = 0; r < 2; r++) {
            int e = lane + r*32, hh = e >> 4, d = e & 15;
            size_t bhi = (size_t)(b0*H_ + hh);
            #pragma unroll
            for (int tp = 0; tp < 2; tp++) {
                int s = s0 + tp*2;
                float2 vq = upk2(acc[0][r][tp]);
                g_qh[(bhi*S_ + s  )*16 + d] = __float2bfloat16(vq.x * QSCALE);
                g_qh[(bhi*S_ + s+1)*16 + d] = __float2bfloat16(vq.y * QSCALE);
                float2 vk = upk2(acc[1][r][tp]);
                g_kh[(bhi*S_ + s  )*16 + d] = __float2bfloat16(vk.x);
                g_kh[(bhi*S_ + s+1)*16 + d] = __float2bfloat16(vk.y);
                float2 vv = upk2(acc[2][r][tp]);
                *(unsigned*)&g_vt[(bhi*16 + d)*S_ + s] = pbf_(vv.x, vv.y);
            }
        }
        __syncwarp();
    }
}

// ============ kernel 2: causal attention via bf16 HMMA ============
__global__ void __launch_bounds__(128, 3) attn_kernel()
{
    const int bidx = blockIdx.x;
    const int qt = 7 - (bidx >> 7);          // heavy tiles first
    const int bh = bidx & 127;
    const int nk = (qt + 1) * 128;
    const int qbase = qt * 128;

    extern __shared__ char smc[];
    __nv_bfloat16* Ks = (__nv_bfloat16*)smc;                    // [nk][16]
    __nv_bfloat16* Vt = (__nv_bfloat16*)(smc + 32768);          // [16][1032]
    __nv_bfloat16* Qs = (__nv_bfloat16*)(smc + 32768 + 33024);  // [128][16]

    const int tid = threadIdx.x, lane = tid & 31, w = tid >> 5;

    {
        const uint4* src = (const uint4*)(g_kh + (size_t)bh * S_ * 16);
        uint4* dst = (uint4*)Ks;
        for (int i = tid; i < nk*2; i += 128) dst[i] = src[i];
    }
    {
        const uint4* src = (const uint4*)(g_qh + ((size_t)bh * S_ + qbase) * 16);
        uint4* dst = (uint4*)Qs;
        dst[tid] = src[tid];
        dst[tid + 128] = src[tid + 128];
    }
    for (int d = w; d < 16; d += 4) {
        const uint4* src = (const uint4*)(g_vt + ((size_t)bh*16 + d) * S_);
        uint4* dst = (uint4*)(Vt + d * 1032);
        for (int i = lane; i < nk/8; i += 32) dst[i] = src[i];
    }
    __syncthreads();

    const int g = lane >> 2, tg = lane & 3;

    unsigned qa[2][4];
    #pragma unroll
    for (int mf = 0; mf < 2; mf++) {
        int rr = w*32 + mf*16 + g;
        qa[mf][0] = *(const unsigned*)&Qs[ rr     *16 + 2*tg    ];
        qa[mf][1] = *(const unsigned*)&Qs[(rr + 8)*16 + 2*tg    ];
        qa[mf][2] = *(const unsigned*)&Qs[ rr     *16 + 2*tg + 8];
        qa[mf][3] = *(const unsigned*)&Qs[(rr + 8)*16 + 2*tg + 8];
    }

    float o[2][2][4];
    #pragma unroll
    for (int mf = 0; mf < 2; mf++)
        #pragma unroll
        for (int dh = 0; dh < 2; dh++)
            o[mf][dh][0] = o[mf][dh][1] = o[mf][dh][2] = o[mf][dh][3] = 0.f;
    float lsum[2][2] = {{0.f,0.f},{0.f,0.f}};

    auto step = [&](int j0, bool MASK) {
        unsigned kb[2][2], vb[2][2];
        #pragma unroll
        for (int kh = 0; kh < 2; kh++) {
            const __nv_bfloat16* kr = Ks + (j0 + kh*8 + g)*16 + 2*tg;
            kb[kh][0] = *(const unsigned*)kr;
            kb[kh][1] = *(const unsigned*)(kr + 8);
        }
        #pragma unroll
        for (int dh = 0; dh < 2; dh++) {
            const __nv_bfloat16* vr = Vt + (dh*8 + g)*1032 + j0 + 2*tg;
            vb[dh][0] = *(const unsigned*)vr;
            vb[dh][1] = *(const unsigned*)(vr + 8);
        }
        #pragma unroll
        for (int mf = 0; mf < 2; mf++) {
            float c[2][4];
            #pragma unroll
            for (int kh = 0; kh < 2; kh++) {
                c[kh][0] = c[kh][1] = c[kh][2] = c[kh][3] = 0.f;
                mma16816(c[kh][0], c[kh][1], c[kh][2], c[kh][3],
                         qa[mf][0], qa[mf][1], qa[mf][2], qa[mf][3],
                         kb[kh][0], kb[kh][1]);
            }
            const int r0 = qbase + w*32 + mf*16 + g, r1 = r0 + 8;
            float p[2][4];
            #pragma unroll
            for (int kh = 0; kh < 2; kh++) {
                int k0 = j0 + kh*8 + 2*tg;
                p[kh][0] = (!MASK || k0     <= r0) ? ex2_(c[kh][0]) : 0.f;
                p[kh][1] = (!MASK || k0 + 1 <= r0) ? ex2_(c[kh][1]) : 0.f;
                p[kh][2] = (!MASK || k0     <= r1) ? ex2_(c[kh][2]) : 0.f;
                p[kh][3] = (!MASK || k0 + 1 <= r1) ? ex2_(c[kh][3]) : 0.f;
            }
            lsum[mf][0] += (p[0][0] + p[0][1]) + (p[1][0] + p[1][1]);
            lsum[mf][1] += (p[0][2] + p[0][3]) + (p[1][2] + p[1][3]);
            unsigned pa0 = pbf_(p[0][0], p[0][1]);
            unsigned pa1 = pbf_(p[0][2], p[0][3]);
            unsigned pa2 = pbf_(p[1][0], p[1][1]);
            unsigned pa3 = pbf_(p[1][2], p[1][3]);
            #pragma unroll
            for (int dh = 0; dh < 2; dh++)
                mma16816(o[mf][dh][0], o[mf][dh][1], o[mf][dh][2], o[mf][dh][3],
                         pa0, pa1, pa2, pa3, vb[dh][0], vb[dh][1]);
        }
    };

    for (int j0 = 0; j0 < qbase; j0 += 16) step(j0, false);
    const int wlast = qbase + w*32 + 31;
    for (int j0 = qbase; j0 < nk; j0 += 16) {
        if (j0 > wlast) break;
        step(j0, true);
    }

    const int b = bh >> 2, h = bh & 3;
    #pragma unroll
    for (int mf = 0; mf < 2; mf++) {
        float l0 = lsum[mf][0], l1 = lsum[mf][1];
        l0 += __shfl_xor_sync(~0u, l0, 1); l0 += __shfl_xor_sync(~0u, l0, 2);
        l1 += __shfl_xor_sync(~0u, l1, 1); l1 += __shfl_xor_sync(~0u, l1, 2);
        float i0 = 1.f / l0, i1 = 1.f / l1;
        int r0 = qbase + w*32 + mf*16 + g;
        float* b0p = g_o + ((size_t)(b*S_ + r0))*64 + h*16;
        float* b1p = b0p + 8*64;
        *(float2*)(b0p + 2*tg)     = make_float2(o[mf][0][0]*i0, o[mf][0][1]*i0);
        *(float2*)(b0p + 8 + 2*tg) = make_float2(o[mf][1][0]*i0, o[mf][1][1]*i0);
        *(float2*)(b1p + 2*tg)     = make_float2(o[mf][0][2]*i1, o[mf][0][3]*i1);
        *(float2*)(b1p + 8 + 2*tg) = make_float2(o[mf][1][2]*i1, o[mf][1][3]*i1);
    }
}

// ============ kernel 3a: x1 = x + av@wo^T  (HMMA, writes out) ============
__global__ void __launch_bounds__(128, 4) mem1_kernel(
    const float* __restrict__ x, float* __restrict__ out)
{
    extern __shared__ char smc[];
    __nv_bfloat16* woB = (__nv_bfloat16*)smc;   // [64][72]

    const int tid = threadIdx.x, lane = tid & 31, w = tid >> 5;
    const int g = lane >> 2, tg = lane & 3;
    const int m0 = blockIdx.x*128 + w*32;

    for (int i = tid; i < 2048; i += 128) {
        int o = i >> 5, j = (i & 31)*2;
        *(unsigned*)&woB[o*72 + j] = ((const unsigned*)g_wob)[i];
    }
    __syncthreads();

    float c[2][8][4];
    #pragma unroll
    for (int mf = 0; mf < 2; mf++)
        #pragma unroll
        for (int nf = 0; nf < 8; nf++)
            c[mf][nf][0] = c[mf][nf][1] = c[mf][nf][2] = c[mf][nf][3] = 0.f;

    #pragma unroll
    for (int ks = 0; ks < 4; ks++) {
        const int k = ks*16 + 2*tg;
        unsigned a[2][4];
        #pragma unroll
        for (int mf = 0; mf < 2; mf++) {
            const float* ar = g_o + (size_t)(m0 + mf*16 + g)*64 + k;
            float2 v0 = *(const float2*)ar;
            float2 v1 = *(const float2*)(ar + 8*64);
            float2 v2 = *(const float2*)(ar + 8);
            float2 v3 = *(const float2*)(ar + 8*64 + 8);
            a[mf][0] = pbf_(v0.x, v0.y);
            a[mf][1] = pbf_(v1.x, v1.y);
            a[mf][2] = pbf_(v2.x, v2.y);
            a[mf][3] = pbf_(v3.x, v3.y);
        }
        #pragma unroll
        for (int nf = 0; nf < 8; nf++) {
            const __nv_bfloat16* br = woB + (nf*8 + g)*72 + k;
            unsigned b0 = *(const unsigned*)br;
            unsigned bq = *(const unsigned*)(br + 8);
            #pragma unroll
            for (int mf = 0; mf < 2; mf++)
                mma16816(c[mf][nf][0], c[mf][nf][1], c[mf][nf][2], c[mf][nf][3],
                         a[mf][0], a[mf][1], a[mf][2], a[mf][3], b0, bq);
        }
    }

    #pragma unroll
    for (int mf = 0; mf < 2; mf++) {
        const int r = m0 + mf*16 + g;
        #pragma unroll
        for (int nf = 0; nf < 8; nf++) {
            int e = nf*8 + 2*tg;
            float2 x0 = *(const float2*)&x[(size_t)r*64 + e];
            float2 x1 = *(const float2*)&x[(size_t)(r+8)*64 + e];
            *(float2*)&out[(size_t)r*64 + e] =
                make_float2(x0.x + c[mf][nf][0], x0.y + c[mf][nf][1]);
            *(float2*)&out[(size_t)(r+8)*64 + e] =
                make_float2(x1.x + c[mf][nf][2], x1.y + c[mf][nf][3]);
        }
    }
}

// ============ kernel 3b: fp32 middle — rmsnorm/mq/l2norm/scores/top-8/gather ============
// warp-per-token, tables-only smem -> high occupancy for latency hiding.
__global__ void __launch_bounds__(256) mem2_kernel(
    const float* __restrict__ mvals, const float* __restrict__ maddr,
    const float* __restrict__ mnw,   const float* __restrict__ mq,
    const float* __restrict__ out)
{
    extern __shared__ float sm[];
    float* mqT  = sm;              // [64][33]
    float* aT   = mqT + 2112;      // [32][65]
    float* mnws = aT + 2080;       // 64
    float* rows = mnws + 64;       // 8*96

    const int tid = threadIdx.x, lane = tid & 31, w = tid >> 5;

    for (int i = tid; i < AD_*E_; i += blockDim.x) {
        int a = i >> 6, e = i & 63;
        mqT[e*33 + a] = mq[i];
    }
    if (tid < 64) mnws[tid] = mnw[tid];
    if (tid < 64) {
        float ssum = 0.f, v[32];
        #pragma unroll
        for (int a = 0; a < 32; a++) { v[a] = maddr[tid*32 + a]; ssum += v[a]*v[a]; }
        float rn = 1.f / fmaxf(sqrtf(ssum), 1e-12f);
        #pragma unroll
        for (int a = 0; a < 32; a++) aT[a*65 + tid] = v[a] * rn;
    }
    __syncthreads();

    float* hrow = rows + w*96;
    float* qrow = hrow + 64;

    for (int tok = blockIdx.x*8 + w; tok < NT_; tok += gridDim.x*8) {
        const int b = tok >> 10;
        float x1a = out[(size_t)tok*64 + lane];
        float x1b = out[(size_t)tok*64 + lane + 32];
        float ss = x1a*x1a + x1b*x1b;
        #pragma unroll
        for (int o = 16; o; o >>= 1) ss += __shfl_xor_sync(~0u, ss, o);
        float rinv = rsqrtf(ss * (1.f/64.f) + 1e-5f);
        hrow[lane]      = x1a * rinv * mnws[lane];
        hrow[lane + 32] = x1b * rinv * mnws[lane + 32];
        __syncwarp();
        float qa = 0.f;
        #pragma unroll
        for (int e = 0; e < 64; e++) qa += hrow[e] * mqT[e*33 + lane];
        float qsm = qa*qa;
        #pragma unroll
        for (int o = 16; o; o >>= 1) qsm += __shfl_xor_sync(~0u, qsm, o);
        float rq = 1.f / fmaxf(sqrtf(qsm), 1e-12f);
        qrow[lane] = qa * rq;
        __syncwarp();
        float sc0 = 0.f, sc1 = 0.f;
        #pragma unroll
        for (int a = 0; a < 32; a++) {
            float qv = qrow[a];
            sc0 += qv * aT[a*65 + lane];
            sc1 += qv * aT[a*65 + lane + 32];
        }
        sc0 *= 4.f; sc1 *= 4.f;
        unsigned f0 = __float_as_uint(sc0);
        unsigned m0 = (f0 & 0x80000000u) ? ~f0 : (f0 | 0x80000000u);
        unsigned key0 = (m0 & 0xFFFFFFC0u) | (unsigned)(63 - lane);
        unsigned f1 = __float_as_uint(sc1);
        unsigned m1 = (f1 & 0x80000000u) ? ~f1 : (f1 | 0x80000000u);
        unsigned key1 = (m1 & 0xFFFFFFC0u) | (unsigned)(31 - lane);
        float tv[8]; int ti[8];
        #pragma unroll
        for (int k = 0; k < 8; k++) {
            unsigned loc = key0 > key1 ? key0 : key1;
            unsigned r = __reduce_max_sync(0xffffffffu, loc);
            int idx = 63 - (int)(r & 63u);
            float vsel = __shfl_sync(0xffffffffu, (idx >= 32) ? sc1 : sc0, idx & 31);
            tv[k] = vsel; ti[k] = idx;
            if (idx == lane)      key0 = 0u;
            if (idx == lane + 32) key1 = 0u;
        }
        float wsum = 0.f, wk8[8];
        #pragma unroll
        for (int k = 0; k < 8; k++) { wk8[k] = __expf(tv[k] - tv[0]); wsum += wk8[k]; }
        float winv = 1.f / wsum;
        const float* mb = mvals + b * NS_ * E_;
        float r0 = 0.f, r1 = 0.f;
        #pragma unroll
        for (int k = 0; k < 8; k++) {
            float wv = wk8[k] * winv;
            const float* mrow = mb + ti[k]*64;
            r0 += wv * mrow[lane];
            r1 += wv * mrow[lane + 32];
        }
        g_rv[(size_t)tok*64 + lane]      = __float2bfloat16(r0);
        g_rv[(size_t)tok*64 + lane + 32] = __float2bfloat16(r1);
    }
}

// ============ kernel 3c: out += rv@mo^T  (HMMA) ============
__global__ void __launch_bounds__(128, 4) mem3_kernel(float* __restrict__ out)
{
    extern __shared__ char smc[];
    __nv_bfloat16* moB = (__nv_bfloat16*)smc;   // [64][72]

    const int tid = threadIdx.x, lane = tid & 31, w = tid >> 5;
    const int g = lane >> 2, tg = lane & 3;
    const int m0 = blockIdx.x*128 + w*32;

    for (int i = tid; i < 2048; i += 128) {
        int o = i >> 5, j = (i & 31)*2;
        *(unsigned*)&moB[o*72 + j] = ((const unsigned*)g_mob)[i];
    }
    __syncthreads();

    float c[2][8][4];
    #pragma unroll
    for (int mf = 0; mf < 2; mf++)
        #pragma unroll
        for (int nf = 0; nf < 8; nf++)
            c[mf][nf][0] = c[mf][nf][1] = c[mf][nf][2] = c[mf][nf][3] = 0.f;

    #pragma unroll
    for (int ks = 0; ks < 4; ks++) {
        const int k = ks*16 + 2*tg;
        unsigned a[2][4];
        #pragma unroll
        for (int mf = 0; mf < 2; mf++) {
            const __nv_bfloat16* ar = g_rv + (size_t)(m0 + mf*16 + g)*64 + k;
            a[mf][0] = *(const unsigned*)ar;
            a[mf][1] = *(const unsigned*)(ar + 8*64);
            a[mf][2] = *(const unsigned*)(ar + 8);
            a[mf][3] = *(const unsigned*)(ar + 8*64 + 8);
        }
        #pragma unroll
        for (int nf = 0; nf < 8; nf++) {
            const __nv_bfloat16* br = moB + (nf*8 + g)*72 + k;
            unsigned b0 = *(const unsigned*)br;
            unsigned bq = *(const unsigned*)(br + 8);
            #pragma unroll
            for (int mf = 0; mf < 2; mf++)
                mma16816(c[mf][nf][0], c[mf][nf][1], c[mf][nf][2], c[mf][nf][3],
                         a[mf][0], a[mf][1], a[mf][2], a[mf][3], b0, bq);
        }
    }

    #pragma unroll
    for (int mf = 0; mf < 2; mf++) {
        const int r = m0 + mf*16 + g;
        #pragma unroll
        for (int nf = 0; nf < 8; nf++) {
            int e = nf*8 + 2*tg;
            float2 o0 = *(float2*)&out[(size_t)r*64 + e];
            float2 o1 = *(float2*)&out[(size_t)(r+8)*64 + e];
            o0.x += c[mf][nf][0]; o0.y += c[mf][nf][1];
            o1.x += c[mf][nf][2]; o1.y += c[mf][nf][3];
            *(float2*)&out[(size_t)r*64 + e]     = o0;
            *(float2*)&out[(size_t)(r+8)*64 + e] = o1;
        }
    }
}

// ============ kernel 4a: FFN GEMM1 via HMMA + fast GELU -> g_hidb ============
__global__ void __launch_bounds__(256, 2) ffn1_kernel(
    const float* __restrict__ fnw, const float* __restrict__ b1,
    const float* __restrict__ out)
{
    extern __shared__ char smc[];
    __nv_bfloat16* w1s = (__nv_bfloat16*)smc;            // [256][72]
    __nv_bfloat16* As  = (__nv_bfloat16*)(smc + 36864);  // [128][72]
    float* b1s = (float*)(smc + 36864 + 18432);          // 256
    float* fns = b1s + 256;                              // 64

    const int tid = threadIdx.x, lane = tid & 31, w = tid >> 5;
    const int g = lane >> 2, tg = lane & 3;
    const int wm = w & 3, nh = w >> 2;
    const int tok0 = blockIdx.x * 128;

    for (int i = tid; i < 256*32; i += 256) {
        int j2 = i*2;
        int o = j2 >> 6, j = j2 & 63;
        *(unsigned*)&w1s[o*72 + j] = ((const unsigned*)g_w1b)[i];
    }
    b1s[tid] = b1[tid];
    if (tid < 64) fns[tid] = fnw[tid];
    __syncthreads();

    if (tid < 128) {
        const float4* xr = (const float4*)(out + (size_t)(tok0 + tid)*64);
        float4 v[16];
        float ss = 0.f;
        #pragma unroll
        for (int i = 0; i < 16; i++) {
            v[i] = xr[i];
            ss += v[i].x*v[i].x + v[i].y*v[i].y + v[i].z*v[i].z + v[i].w*v[i].w;
        }
        float rinv = rsqrtf(ss * (1.f/64.f) + 1e-5f);
        #pragma unroll
        for (int i = 0; i < 16; i++) {
            *(unsigned*)&As[tid*72 + 4*i]     = pbf_(v[i].x*rinv*fns[4*i],   v[i].y*rinv*fns[4*i+1]);
            *(unsigned*)&As[tid*72 + 4*i + 2] = pbf_(v[i].z*rinv*fns[4*i+2], v[i].w*rinv*fns[4*i+3]);
        }
    }
    __syncthreads();

    unsigned a[4][2][4];
    #pragma unroll
    for (int ks = 0; ks < 4; ks++)
        #pragma unroll
        for (int mf = 0; mf < 2; mf++) {
            int r = wm*32 + mf*16 + g;
            int k = ks*16 + 2*tg;
            a[ks][mf][0] = *(const unsigned*)&As[ r      *72 + k];
            a[ks][mf][1] = *(const unsigned*)&As[(r + 8) *72 + k];
            a[ks][mf][2] = *(const unsigned*)&As[ r      *72 + k + 8];
            a[ks][mf][3] = *(const unsigned*)&As[(r + 8) *72 + k + 8];
        }

    #pragma unroll
    for (int ch = 0; ch < 2; ch++) {
        const int n0 = nh*128 + ch*64;
        float c[2][8][4];
        #pragma unroll
        for (int mf = 0; mf < 2; mf++)
            #pragma unroll
            for (int nf = 0; nf < 8; nf++)
                c[mf][nf][0] = c[mf][nf][1] = c[mf][nf][2] = c[mf][nf][3] = 0.f;

        #pragma unroll
        for (int ks = 0; ks < 4; ks++) {
            #pragma unroll
            for (int nf = 0; nf < 8; nf++) {
                const __nv_bfloat16* br = w1s + (n0 + nf*8 + g)*72 + ks*16 + 2*tg;
                unsigned b0 = *(const unsigned*)br;
                unsigned bq = *(const unsigned*)(br + 8);
                #pragma unroll
                for (int mf = 0; mf < 2; mf++)
                    mma16816(c[mf][nf][0], c[mf][nf][1], c[mf][nf][2], c[mf][nf][3],
                             a[ks][mf][0], a[ks][mf][1], a[ks][mf][2], a[ks][mf][3],
                             b0, bq);
            }
        }

        #pragma unroll
        for (int mf = 0; mf < 2; mf++) {
            const int r = tok0 + wm*32 + mf*16 + g;
            #pragma unroll
            for (int nf = 0; nf < 8; nf++) {
                int e = n0 + nf*8 + 2*tg;
                float be0 = b1s[e], be1 = b1s[e+1];
                *(unsigned*)&g_hidb[(size_t)r*256 + e] =
                    pbf_(gelu_(c[mf][nf][0] + be0), gelu_(c[mf][nf][1] + be1));
                *(unsigned*)&g_hidb[(size_t)(r+8)*256 + e] =
                    pbf_(gelu_(c[mf][nf][2] + be0), gelu_(c[mf][nf][3] + be1));
            }
        }
    }
}

// ============ kernel 4b: FFN GEMM2 via HMMA + residual ============
__global__ void __launch_bounds__(128, 4) ffn2_kernel(
    const float* __restrict__ b2, float* __restrict__ out)
{
    extern __shared__ char smc[];
    __nv_bfloat16* w2s = (__nv_bfloat16*)smc;   // [64][264]
    float* b2s = (float*)(smc + 64*264*2);

    const int tid = threadIdx.x, lane = tid & 31, w = tid >> 5;
    const int g = lane >> 2, tg = lane & 3;
    const int tok0 = blockIdx.x * 128;

    for (int i = tid; i < 64*128; i += 128) {
        int j2 = i*2;
        int e = j2 >> 8, o = j2 & 255;
        *(unsigned*)&w2s[e*264 + o] = ((const unsigned*)g_w2b)[i];
    }
    if (tid < 64) b2s[tid] = b2[tid];
    __syncthreads();

    float c[2][8][4];
    #pragma unroll
    for (int mf = 0; mf < 2; mf++)
        #pragma unroll
        for (int nf = 0; nf < 8; nf++)
            c[mf][nf][0] = c[mf][nf][1] = c[mf][nf][2] = c[mf][nf][3] = 0.f;

    const int m0 = tok0 + w*32;
    #pragma unroll 4
    for (int ks = 0; ks < 16; ks++) {
        const int k = ks*16 + 2*tg;
        unsigned a[2][4];
        #pragma unroll
        for (int mf = 0; mf < 2; mf++) {
            const __nv_bfloat16* ar = g_hidb + (size_t)(m0 + mf*16 + g)*256 + k;
            a[mf][0] = *(const unsigned*)ar;
            a[mf][1] = *(const unsigned*)(ar + 8*256);
            a[mf][2] = *(const unsigned*)(ar + 8);
            a[mf][3] = *(const unsigned*)(ar + 8*256 + 8);
        }
        #pragma unroll
        for (int nf = 0; nf < 8; nf++) {
            const __nv_bfloat16* br = w2s + (nf*8 + g)*264 + k;
            unsigned b0 = *(const unsigned*)br;
            unsigned bq = *(const unsigned*)(br + 8);
            #pragma unroll
            for (int mf = 0; mf < 2; mf++)
                mma16816(c[mf][nf][0], c[mf][nf][1], c[mf][nf][2], c[mf][nf][3],
                         a[mf][0], a[mf][1], a[mf][2], a[mf][3], b0, bq);
        }
    }

    #pragma unroll
    for (int mf = 0; mf < 2; mf++) {
        const int r = m0 + mf*16 + g;
        #pragma unroll
        for (int nf = 0; nf < 8; nf++) {
            int e = nf*8 + 2*tg;
            float2 o0 = *(float2*)&out[(size_t)r*64 + e];
            float2 o1 = *(float2*)&out[(size_t)(r+8)*64 + e];
            o0.x += b2s[e]   + c[mf][nf][0];
            o0.y += b2s[e+1] + c[mf][nf][1];
            o1.x += b2s[e]   + c[mf][nf][2];
            o1.y += b2s[e+1] + c[mf][nf][3];
            *(float2*)&out[(size_t)r*64 + e]     = o0;
            *(float2*)&out[(size_t)(r+8)*64 + e] = o1;
        }
    }
}

// ============ launch ============
extern "C" void kernel_launch(void* const* d_in, const int* in_sizes, int n_in,
                              void* d_out, int out_size)
{
    const float* x     = (const float*)d_in[0];
    const float* maddr = (const float*)d_in[1];
    const float* mvals = (const float*)d_in[2];
    const float* anw   = (const float*)d_in[3];
    const float* wq    = (const float*)d_in[4];
    const float* wk    = (const float*)d_in[5];
    const float* wv    = (const float*)d_in[6];
    const float* wo    = (const float*)d_in[7];
    const float* mnw   = (const float*)d_in[8];
    const float* mq    = (const float*)d_in[9];
    const float* mo    = (const float*)d_in[10];
    const float* fnw   = (const float*)d_in[11];
    const float* w1    = (const float*)d_in[12];
    const float* b1    = (const float*)d_in[13];
    const float* w2    = (const float*)d_in[14];
    const float* b2    = (const float*)d_in[15];
    float* out = (float*)d_out;

    const int QKV_SMEM  = (3*4224 + 64) * 4 + 8*128*8;            // 59,136
    const int ATT_SMEM  = 32768 + 33024 + 4096;                   // 69,888
    const int MEM1_SMEM = 64*72*2;                                // 9,216
    const int MEM2_SMEM = (2112 + 2080 + 64 + 8*96) * 4;          // 20,096
    const int FFN1_SMEM = 36864 + 18432 + (256 + 64) * 4;         // 56,576
    const int FFN2_SMEM = 64*264*2 + 64*4;                        // 34,048

    cudaFuncSetAttribute(qkv_kernel, cudaFuncAttributeMaxDynamicSharedMemorySize, QKV_SMEM);
    cudaFuncSetAttribute(attn_kernel, cudaFuncAttributeMaxDynamicSharedMemorySize, ATT_SMEM);
    cudaFuncSetAttribute(mem1_kernel, cudaFuncAttributeMaxDynamicSharedMemorySize, MEM1_SMEM);
    cudaFuncSetAttribute(mem2_kernel, cudaFuncAttributeMaxDynamicSharedMemorySize, MEM2_SMEM);
    cudaFuncSetAttribute(mem3_kernel, cudaFuncAttributeMaxDynamicSharedMemorySize, MEM1_SMEM);
    cudaFuncSetAttribute(ffn1_kernel, cudaFuncAttributeMaxDynamicSharedMemorySize, FFN1_SMEM);
    cudaFuncSetAttribute(ffn2_kernel, cudaFuncAttributeMaxDynamicSharedMemorySize, FFN2_SMEM);

    cvt_kernel<<<64, 256>>>(w1, w2, wo, mo);
    qkv_kernel<<<296, 256, QKV_SMEM>>>(x, anw, wq, wk, wv);
    attn_kernel<<<1024, 128, ATT_SMEM>>>();
    mem1_kernel<<<256, 128, MEM1_SMEM>>>(x, out);
    mem2_kernel<<<592, 256, MEM2_SMEM>>>(mvals, maddr, mnw, mq, out);
    mem3_kernel<<<256, 128, MEM1_SMEM>>>(out);
    ffn1_kernel<<<256, 256, FFN1_SMEM>>>(fnw, b1, out);
    ffn2_kernel<<<256, 128, FFN2_SMEM>>>(b2, out);
}